// round 2
// baseline (speedup 1.0000x reference)
#include <cuda_runtime.h>

#define BB   16
#define CC   256
#define CHALF 128
#define CQ   32
#define HW   9216
#define NPIXF 9216.0f

// ---- scratch (device globals; no runtime allocation allowed) ----
__device__ float g_feat[(size_t)BB*CC*HW];     // 151 MB
__device__ float g_Qn [(size_t)BB*CQ*HW];      // 18.9 MB
__device__ float g_Kn [(size_t)BB*CQ*HW];      // 18.9 MB
__device__ float g_G  [BB*CQ*CC];
__device__ float g_matrix[BB*CQ*CC];
__device__ float g_fsum[BB*CC];
__device__ float g_knsum[BB*CQ];
__device__ float g_vsum[BB*CC];
__device__ float g_bn_a[CC];
__device__ float g_bn_b[CC];

// ---------------------------------------------------------------
// K0: zero accumulators + fold BN into (a, b):  y = relu(acc*a + b)
// ---------------------------------------------------------------
__global__ void k_setup(const float* __restrict__ bn_scale, const float* __restrict__ bn_bias,
                        const float* __restrict__ bn_mean,  const float* __restrict__ bn_var) {
    int t = blockIdx.x * blockDim.x + threadIdx.x;
    int stride = gridDim.x * blockDim.x;
    for (int i = t; i < BB*CQ*CC; i += stride) g_G[i] = 0.f;
    for (int i = t; i < BB*CC;    i += stride) g_fsum[i] = 0.f;
    for (int i = t; i < BB*CQ;    i += stride) g_knsum[i] = 0.f;
    if (t < CC) {
        float inv = rsqrtf(bn_var[t] + 1e-5f);
        float a = bn_scale[t] * inv;
        g_bn_a[t] = a;
        g_bn_b[t] = bn_bias[t] - bn_mean[t] * a;
    }
}

// ---------------------------------------------------------------
// K1: feat = relu(bn(conv1x1(concat(fsp,fcp))))   [B,256,9216]
//     128x128 block tile, K-step 8, 8x8 per-thread; also Σ_n feat
// ---------------------------------------------------------------
__global__ __launch_bounds__(256) void k_conv(const float* __restrict__ fsp,
                                              const float* __restrict__ fcp,
                                              const float* __restrict__ Wc) {
    __shared__ __align__(16) float Ws[8][128];
    __shared__ __align__(16) float Xs[8][128];
    __shared__ float red[128][17];
    const int t  = threadIdx.x;
    const int tx = t & 15, ty = t >> 4;
    const int n0 = blockIdx.x * 128;
    const int m0 = blockIdx.y * 128;
    const int b  = blockIdx.z;

    float acc[8][8];
    #pragma unroll
    for (int i = 0; i < 8; i++)
        #pragma unroll
        for (int j = 0; j < 8; j++) acc[i][j] = 0.f;

    const int w_o = t >> 1;
    const int w_k = (t & 1) * 4;
    const int x_k = t >> 5;
    const int x_n = (t & 31) * 4;
    const float* xh0 = fsp + (size_t)b * CHALF * HW;
    const float* xh1 = fcp + (size_t)b * CHALF * HW;

    for (int k0 = 0; k0 < CC; k0 += 8) {
        float4 wv = *(const float4*)&Wc[(size_t)(m0 + w_o) * CC + k0 + w_k];
        Ws[w_k + 0][w_o] = wv.x; Ws[w_k + 1][w_o] = wv.y;
        Ws[w_k + 2][w_o] = wv.z; Ws[w_k + 3][w_o] = wv.w;
        int c = k0 + x_k;
        const float* xp = (c < CHALF) ? (xh0 + (size_t)c * HW) : (xh1 + (size_t)(c - CHALF) * HW);
        *(float4*)&Xs[x_k][x_n] = *(const float4*)&xp[n0 + x_n];
        __syncthreads();
        #pragma unroll
        for (int kk = 0; kk < 8; kk++) {
            float4 w0 = *(float4*)&Ws[kk][ty * 8];
            float4 w1 = *(float4*)&Ws[kk][ty * 8 + 4];
            float4 x0 = *(float4*)&Xs[kk][tx * 8];
            float4 x1 = *(float4*)&Xs[kk][tx * 8 + 4];
            float wr[8] = {w0.x, w0.y, w0.z, w0.w, w1.x, w1.y, w1.z, w1.w};
            float xr[8] = {x0.x, x0.y, x0.z, x0.w, x1.x, x1.y, x1.z, x1.w};
            #pragma unroll
            for (int i = 0; i < 8; i++)
                #pragma unroll
                for (int j = 0; j < 8; j++)
                    acc[i][j] = fmaf(wr[i], xr[j], acc[i][j]);
        }
        __syncthreads();
    }

    #pragma unroll
    for (int i = 0; i < 8; i++) {
        int o = m0 + ty * 8 + i;
        float a  = g_bn_a[o];
        float bc = g_bn_b[o];
        float rs = 0.f;
        float v[8];
        #pragma unroll
        for (int j = 0; j < 8; j++) {
            float y = fmaxf(fmaf(acc[i][j], a, bc), 0.f);
            v[j] = y; rs += y;
        }
        size_t base = ((size_t)b * CC + o) * HW + n0 + tx * 8;
        float4 s0 = {v[0], v[1], v[2], v[3]};
        float4 s1 = {v[4], v[5], v[6], v[7]};
        *(float4*)&g_feat[base]     = s0;
        *(float4*)&g_feat[base + 4] = s1;
        red[ty * 8 + i][tx] = rs;
    }
    __syncthreads();
    if (t < 128) {
        float s = 0.f;
        #pragma unroll
        for (int j = 0; j < 16; j++) s += red[t][j];
        atomicAdd(&g_fsum[b * CC + m0 + t], s);
    }
}

// ---------------------------------------------------------------
// K2: QK = [q_w;k_w] @ feat (+bias), per-pixel L2 norm over channels,
//     writes Qn, Kn; accumulates knsum[b][m] = Σ_n Kn
// ---------------------------------------------------------------
__global__ __launch_bounds__(256) void k_qk(const float* __restrict__ qw, const float* __restrict__ qb,
                                            const float* __restrict__ kw, const float* __restrict__ kb) {
    __shared__ __align__(16) float Ws[8][64];
    __shared__ __align__(16) float Xs[8][128];
    __shared__ float qk[64][129];
    __shared__ float part[32][8];
    const int t  = threadIdx.x;
    const int tx = t & 15, ty = t >> 4;       // n = tx*8, m = ty*4
    const int n0 = blockIdx.x * 128;
    const int b  = blockIdx.y;

    float acc[4][8];
    #pragma unroll
    for (int i = 0; i < 4; i++)
        #pragma unroll
        for (int j = 0; j < 8; j++) acc[i][j] = 0.f;

    const int w_m = t >> 2;
    const int w_k = (t & 3) * 2;
    const int x_k = t >> 5;
    const int x_n = (t & 31) * 4;
    const float* wrow = (w_m < 32) ? (qw + (size_t)w_m * CC) : (kw + (size_t)(w_m - 32) * CC);
    const float* fb = g_feat + (size_t)b * CC * HW;

    for (int k0 = 0; k0 < CC; k0 += 8) {
        float2 wv = *(const float2*)&wrow[k0 + w_k];
        Ws[w_k][w_m] = wv.x; Ws[w_k + 1][w_m] = wv.y;
        *(float4*)&Xs[x_k][x_n] = *(const float4*)&fb[(size_t)(k0 + x_k) * HW + n0 + x_n];
        __syncthreads();
        #pragma unroll
        for (int kk = 0; kk < 8; kk++) {
            float4 w  = *(float4*)&Ws[kk][ty * 4];
            float4 x0 = *(float4*)&Xs[kk][tx * 8];
            float4 x1 = *(float4*)&Xs[kk][tx * 8 + 4];
            float wr[4] = {w.x, w.y, w.z, w.w};
            float xr[8] = {x0.x, x0.y, x0.z, x0.w, x1.x, x1.y, x1.z, x1.w};
            #pragma unroll
            for (int i = 0; i < 4; i++)
                #pragma unroll
                for (int j = 0; j < 8; j++)
                    acc[i][j] = fmaf(wr[i], xr[j], acc[i][j]);
        }
        __syncthreads();
    }

    #pragma unroll
    for (int mi = 0; mi < 4; mi++) {
        int m = ty * 4 + mi;
        float bias = (m < 32) ? qb[m] : kb[m - 32];
        #pragma unroll
        for (int j = 0; j < 8; j++) qk[m][tx * 8 + j] = acc[mi][j] + bias;
    }
    __syncthreads();

    {   // per-pixel L2 normalize (h=0 -> Q, h=1 -> K)
        int n = t & 127, h = t >> 7;
        float ss = 0.f;
        #pragma unroll
        for (int m = 0; m < 32; m++) { float v = qk[h * 32 + m][n]; ss = fmaf(v, v, ss); }
        float inv = rsqrtf(ss);
        float* gout = (h == 0) ? g_Qn : g_Kn;
        size_t base = (size_t)b * CQ * HW + n0 + n;
        #pragma unroll
        for (int m = 0; m < 32; m++) {
            float v = qk[h * 32 + m][n] * inv;
            qk[h * 32 + m][n] = v;
            gout[base + (size_t)m * HW] = v;
        }
    }
    __syncthreads();
    {   // knsum partial
        int m = t >> 3, seg = t & 7;
        float s = 0.f;
        #pragma unroll
        for (int j = 0; j < 16; j++) s += qk[32 + m][seg * 16 + j];
        part[m][seg] = s;
    }
    __syncthreads();
    if (t < 32) {
        float s = 0.f;
        #pragma unroll
        for (int j = 0; j < 8; j++) s += part[t][j];
        atomicAdd(&g_knsum[b * CQ + t], s);
    }
}

// ---------------------------------------------------------------
// K3: G[b][m][c] = Σ_n Kn[b][m][n] * feat[b][c][n]  (split-K over n)
// ---------------------------------------------------------------
__global__ __launch_bounds__(256) void k_G() {
    __shared__ __align__(16) float Kns[32][36];
    __shared__ __align__(16) float fsT[32][256];
    const int t  = threadIdx.x;
    const int tx = t & 31, ty = t >> 5;      // c = tx*8, m = ty*4
    const int b  = blockIdx.y;
    const int nchunk0 = blockIdx.x * 576;

    float acc[4][8];
    #pragma unroll
    for (int i = 0; i < 4; i++)
        #pragma unroll
        for (int j = 0; j < 8; j++) acc[i][j] = 0.f;

    const int km = t >> 3;
    const int kn = (t & 7) * 4;
    const float* Knb = g_Kn + (size_t)b * CQ * HW;
    const float* fb  = g_feat + (size_t)b * CC * HW;

    for (int s = 0; s < 18; s++) {
        int nb = nchunk0 + s * 32;
        float4 kv = *(const float4*)&Knb[(size_t)km * HW + nb + kn];
        Kns[kn + 0][km] = kv.x; Kns[kn + 1][km] = kv.y;
        Kns[kn + 2][km] = kv.z; Kns[kn + 3][km] = kv.w;
        const float* fr = fb + (size_t)t * HW + nb;
        #pragma unroll
        for (int j = 0; j < 8; j++) {
            float4 fv = *(const float4*)&fr[j * 4];
            fsT[j * 4 + 0][t] = fv.x; fsT[j * 4 + 1][t] = fv.y;
            fsT[j * 4 + 2][t] = fv.z; fsT[j * 4 + 3][t] = fv.w;
        }
        __syncthreads();
        #pragma unroll
        for (int n = 0; n < 32; n++) {
            float4 k4 = *(float4*)&Kns[n][ty * 4];
            float4 f0 = *(float4*)&fsT[n][tx * 8];
            float4 f1 = *(float4*)&fsT[n][tx * 8 + 4];
            float kr[4] = {k4.x, k4.y, k4.z, k4.w};
            float fr8[8] = {f0.x, f0.y, f0.z, f0.w, f1.x, f1.y, f1.z, f1.w};
            #pragma unroll
            for (int i = 0; i < 4; i++)
                #pragma unroll
                for (int j = 0; j < 8; j++)
                    acc[i][j] = fmaf(kr[i], fr8[j], acc[i][j]);
        }
        __syncthreads();
    }
    #pragma unroll
    for (int i = 0; i < 4; i++)
        #pragma unroll
        for (int j = 0; j < 8; j++)
            atomicAdd(&g_G[((size_t)b * CQ + ty * 4 + i) * CC + tx * 8 + j], acc[i][j]);
}

// ---------------------------------------------------------------
// K4: matrix = G @ v_w^T + v_b ⊗ knsum ;  vsum = v_w @ fsum + N*v_b
// ---------------------------------------------------------------
__global__ __launch_bounds__(256) void k_matrix(const float* __restrict__ vw, const float* __restrict__ vb) {
    __shared__ __align__(16) float GsT[32][36];
    __shared__ __align__(16) float vwTs[32][256];
    __shared__ float fsums[256];
    const int t  = threadIdx.x;
    const int b  = blockIdx.x;
    const int tx = t & 31, ty = t >> 5;      // c = tx*8, m = ty*4

    float acc[4][8];
    #pragma unroll
    for (int i = 0; i < 4; i++)
        #pragma unroll
        for (int j = 0; j < 8; j++) acc[i][j] = 0.f;
    float vs = 0.f;

    fsums[t] = g_fsum[b * CC + t];
    const int gm = t & 31;
    const int gc = (t >> 5) * 4;

    for (int c0 = 0; c0 < CC; c0 += 32) {
        float4 gv = *(const float4*)&g_G[((size_t)b * CQ + gm) * CC + c0 + gc];
        GsT[gc + 0][gm] = gv.x; GsT[gc + 1][gm] = gv.y;
        GsT[gc + 2][gm] = gv.z; GsT[gc + 3][gm] = gv.w;
        const float* vr = vw + (size_t)t * CC + c0;
        #pragma unroll
        for (int j = 0; j < 8; j++) {
            float4 vv = *(const float4*)&vr[j * 4];
            vwTs[j * 4 + 0][t] = vv.x; vwTs[j * 4 + 1][t] = vv.y;
            vwTs[j * 4 + 2][t] = vv.z; vwTs[j * 4 + 3][t] = vv.w;
        }
        __syncthreads();
        #pragma unroll
        for (int cl = 0; cl < 32; cl++) {
            float4 g4 = *(float4*)&GsT[cl][ty * 4];
            float4 v0 = *(float4*)&vwTs[cl][tx * 8];
            float4 v1 = *(float4*)&vwTs[cl][tx * 8 + 4];
            float gr[4] = {g4.x, g4.y, g4.z, g4.w};
            float vr8[8] = {v0.x, v0.y, v0.z, v0.w, v1.x, v1.y, v1.z, v1.w};
            #pragma unroll
            for (int i = 0; i < 4; i++)
                #pragma unroll
                for (int j = 0; j < 8; j++)
                    acc[i][j] = fmaf(gr[i], vr8[j], acc[i][j]);
            vs = fmaf(vwTs[cl][t], fsums[c0 + cl], vs);
        }
        __syncthreads();
    }
    float kn[4];
    #pragma unroll
    for (int i = 0; i < 4; i++) kn[i] = g_knsum[b * CQ + ty * 4 + i];
    #pragma unroll
    for (int i = 0; i < 4; i++)
        #pragma unroll
        for (int j = 0; j < 8; j++) {
            int c = tx * 8 + j;
            g_matrix[((size_t)b * CQ + ty * 4 + i) * CC + c] = acc[i][j] + vb[c] * kn[i];
        }
    g_vsum[b * CC + t] = vs + NPIXF * vb[t];
}

// ---------------------------------------------------------------
// K5: per pixel: ms = matrix^T @ Qn + vsum ; tailor ; fused epilogue
//     out = feat*(feat + gamma*ms*tailor) + feat
// ---------------------------------------------------------------
__global__ __launch_bounds__(256) void k_final(const float* __restrict__ gamma, float* __restrict__ out) {
    __shared__ __align__(16) float ms[32][256];
    __shared__ __align__(16) float Qns[32][64];
    __shared__ float tails[64];
    __shared__ float vsums[256];
    __shared__ float kse[32];
    const int t  = threadIdx.x;
    const int tx = t & 7, ty = t >> 3;       // n = tx*8, c = ty*8
    const int n0 = blockIdx.x * 64;
    const int b  = blockIdx.y;

    {
        const float* mp = g_matrix + (size_t)b * CQ * CC;
        float* msf = &ms[0][0];
        #pragma unroll
        for (int j = 0; j < 8; j++) {
            int idx = t * 32 + j * 4;
            *(float4*)&msf[idx] = *(const float4*)&mp[idx];
        }
    }
    {
        int m = t >> 3, nl = (t & 7) * 8;
        const float* qp = g_Qn + ((size_t)b * CQ + m) * HW + n0 + nl;
        *(float4*)&Qns[m][nl]     = *(const float4*)&qp[0];
        *(float4*)&Qns[m][nl + 4] = *(const float4*)&qp[4];
    }
    vsums[t] = g_vsum[b * CC + t];
    if (t < 32) kse[t] = g_knsum[b * CQ + t] + 1e-6f;
    __syncthreads();
    if (t < 64) {
        float s = 0.f;
        #pragma unroll
        for (int m = 0; m < 32; m++) s = fmaf(Qns[m][t], kse[m], s);
        tails[t] = 1.0f / (NPIXF + s);
    }
    __syncthreads();

    float acc[8][8];
    #pragma unroll
    for (int i = 0; i < 8; i++)
        #pragma unroll
        for (int j = 0; j < 8; j++) acc[i][j] = 0.f;

    #pragma unroll 4
    for (int k = 0; k < 32; k++) {
        float4 m0v = *(float4*)&ms[k][ty * 8];
        float4 m1v = *(float4*)&ms[k][ty * 8 + 4];
        float4 q0  = *(float4*)&Qns[k][tx * 8];
        float4 q1  = *(float4*)&Qns[k][tx * 8 + 4];
        float mr[8] = {m0v.x, m0v.y, m0v.z, m0v.w, m1v.x, m1v.y, m1v.z, m1v.w};
        float qr[8] = {q0.x, q0.y, q0.z, q0.w, q1.x, q1.y, q1.z, q1.w};
        #pragma unroll
        for (int i = 0; i < 8; i++)
            #pragma unroll
            for (int j = 0; j < 8; j++)
                acc[i][j] = fmaf(mr[i], qr[j], acc[i][j]);
    }

    float gw = gamma[0];
    #pragma unroll
    for (int i = 0; i < 8; i++) {
        int c = ty * 8 + i;
        float vsc = vsums[c];
        size_t base = ((size_t)b * CC + c) * HW + n0 + tx * 8;
        float4 f0 = *(const float4*)&g_feat[base];
        float4 f1 = *(const float4*)&g_feat[base + 4];
        float fv[8] = {f0.x, f0.y, f0.z, f0.w, f1.x, f1.y, f1.z, f1.w};
        float o[8];
        #pragma unroll
        for (int j = 0; j < 8; j++) {
            float msv = acc[i][j] + vsc;
            float wv  = msv * tails[tx * 8 + j];
            float f   = fv[j];
            o[j] = fmaf(f, fmaf(gw, wv, f), f);   // f*(f + g*wv) + f
        }
        float4 s0 = {o[0], o[1], o[2], o[3]};
        float4 s1 = {o[4], o[5], o[6], o[7]};
        *(float4*)&out[base]     = s0;
        *(float4*)&out[base + 4] = s1;
    }
}

// ---------------------------------------------------------------
extern "C" void kernel_launch(void* const* d_in, const int* in_sizes, int n_in,
                              void* d_out, int out_size) {
    const float* fsp      = (const float*)d_in[0];
    const float* fcp      = (const float*)d_in[1];
    const float* conv_w   = (const float*)d_in[2];
    const float* bn_scale = (const float*)d_in[3];
    const float* bn_bias  = (const float*)d_in[4];
    const float* bn_mean  = (const float*)d_in[5];
    const float* bn_var   = (const float*)d_in[6];
    const float* gamma    = (const float*)d_in[7];
    const float* q_w      = (const float*)d_in[8];
    const float* q_b      = (const float*)d_in[9];
    const float* k_w      = (const float*)d_in[10];
    const float* k_b      = (const float*)d_in[11];
    const float* v_w      = (const float*)d_in[12];
    const float* v_b      = (const float*)d_in[13];
    float* out = (float*)d_out;

    k_setup<<<128, 256>>>(bn_scale, bn_bias, bn_mean, bn_var);
    k_conv  <<<dim3(72, 2, 16), 256>>>(fsp, fcp, conv_w);
    k_qk    <<<dim3(72, 16),    256>>>(q_w, q_b, k_w, k_b);
    k_G     <<<dim3(16, 16),    256>>>();
    k_matrix<<<16,              256>>>(v_w, v_b);
    k_final <<<dim3(144, 16),   256>>>(gamma, out);
}

// round 4
// speedup vs baseline: 1.0050x; 1.0050x over previous
#include <cuda_runtime.h>

#define BB   16
#define CC   256
#define CHALF 128
#define CQ   32
#define HW   9216
#define NPIXF 9216.0f

// ---- scratch (device globals; no runtime allocation allowed) ----
__device__ float g_feat[(size_t)BB*CC*HW];     // 151 MB
__device__ float g_Qn [(size_t)BB*CQ*HW];      // 18.9 MB
__device__ float g_Kn [(size_t)BB*CQ*HW];      // 18.9 MB
__device__ float g_G  [BB*CQ*CC];
__device__ float g_matrix[BB*CQ*CC];
__device__ float g_fsum[BB*CC];
__device__ float g_knsum[BB*CQ];
__device__ float g_vsum[BB*CC];
__device__ float g_bn_a[CC];
__device__ float g_bn_b[CC];

// ---------------------------------------------------------------
// K0: zero accumulators + fold BN into (a, b):  y = relu(acc*a + b)
// ---------------------------------------------------------------
__global__ void k_setup(const float* __restrict__ bn_scale, const float* __restrict__ bn_bias,
                        const float* __restrict__ bn_mean,  const float* __restrict__ bn_var) {
    int t = blockIdx.x * blockDim.x + threadIdx.x;
    int stride = gridDim.x * blockDim.x;
    for (int i = t; i < BB*CQ*CC; i += stride) g_G[i] = 0.f;
    for (int i = t; i < BB*CC;    i += stride) g_fsum[i] = 0.f;
    for (int i = t; i < BB*CQ;    i += stride) g_knsum[i] = 0.f;
    if (t < CC) {
        float inv = rsqrtf(bn_var[t] + 1e-5f);
        float a = bn_scale[t] * inv;
        g_bn_a[t] = a;
        g_bn_b[t] = bn_bias[t] - bn_mean[t] * a;
    }
}

// ---------------------------------------------------------------
// K1: feat = relu(bn(conv1x1(concat(fsp,fcp))))   [B,256,9216]
//     128x128 block tile, K-step 8, 8x8 per-thread; also Σ_n feat
// ---------------------------------------------------------------
__global__ __launch_bounds__(256) void k_conv(const float* __restrict__ fsp,
                                              const float* __restrict__ fcp,
                                              const float* __restrict__ Wc) {
    __shared__ __align__(16) float Ws[8][128];
    __shared__ __align__(16) float Xs[8][128];
    __shared__ float red[128][17];
    const int t  = threadIdx.x;
    const int tx = t & 15, ty = t >> 4;
    const int n0 = blockIdx.x * 128;
    const int m0 = blockIdx.y * 128;
    const int b  = blockIdx.z;

    float acc[8][8];
    #pragma unroll
    for (int i = 0; i < 8; i++)
        #pragma unroll
        for (int j = 0; j < 8; j++) acc[i][j] = 0.f;

    const int w_o = t >> 1;
    const int w_k = (t & 1) * 4;
    const int x_k = t >> 5;
    const int x_n = (t & 31) * 4;
    const float* xh0 = fsp + (size_t)b * CHALF * HW;
    const float* xh1 = fcp + (size_t)b * CHALF * HW;

    for (int k0 = 0; k0 < CC; k0 += 8) {
        float4 wv = *(const float4*)&Wc[(size_t)(m0 + w_o) * CC + k0 + w_k];
        Ws[w_k + 0][w_o] = wv.x; Ws[w_k + 1][w_o] = wv.y;
        Ws[w_k + 2][w_o] = wv.z; Ws[w_k + 3][w_o] = wv.w;
        int c = k0 + x_k;
        const float* xp = (c < CHALF) ? (xh0 + (size_t)c * HW) : (xh1 + (size_t)(c - CHALF) * HW);
        *(float4*)&Xs[x_k][x_n] = *(const float4*)&xp[n0 + x_n];
        __syncthreads();
        #pragma unroll
        for (int kk = 0; kk < 8; kk++) {
            float4 w0 = *(float4*)&Ws[kk][ty * 8];
            float4 w1 = *(float4*)&Ws[kk][ty * 8 + 4];
            float4 x0 = *(float4*)&Xs[kk][tx * 8];
            float4 x1 = *(float4*)&Xs[kk][tx * 8 + 4];
            float wr[8] = {w0.x, w0.y, w0.z, w0.w, w1.x, w1.y, w1.z, w1.w};
            float xr[8] = {x0.x, x0.y, x0.z, x0.w, x1.x, x1.y, x1.z, x1.w};
            #pragma unroll
            for (int i = 0; i < 8; i++)
                #pragma unroll
                for (int j = 0; j < 8; j++)
                    acc[i][j] = fmaf(wr[i], xr[j], acc[i][j]);
        }
        __syncthreads();
    }

    #pragma unroll
    for (int i = 0; i < 8; i++) {
        int o = m0 + ty * 8 + i;
        float a  = g_bn_a[o];
        float bc = g_bn_b[o];
        float rs = 0.f;
        float v[8];
        #pragma unroll
        for (int j = 0; j < 8; j++) {
            float y = fmaxf(fmaf(acc[i][j], a, bc), 0.f);
            v[j] = y; rs += y;
        }
        size_t base = ((size_t)b * CC + o) * HW + n0 + tx * 8;
        float4 s0 = {v[0], v[1], v[2], v[3]};
        float4 s1 = {v[4], v[5], v[6], v[7]};
        *(float4*)&g_feat[base]     = s0;
        *(float4*)&g_feat[base + 4] = s1;
        red[ty * 8 + i][tx] = rs;
    }
    __syncthreads();
    if (t < 128) {
        float s = 0.f;
        #pragma unroll
        for (int j = 0; j < 16; j++) s += red[t][j];
        atomicAdd(&g_fsum[b * CC + m0 + t], s);
    }
}

// ---------------------------------------------------------------
// K2: QK = [q_w;k_w] @ feat (+bias), per-pixel L2 norm over channels,
//     writes Qn, Kn; accumulates knsum[b][m] = Σ_n Kn
// ---------------------------------------------------------------
__global__ __launch_bounds__(256) void k_qk(const float* __restrict__ qw, const float* __restrict__ qb,
                                            const float* __restrict__ kw, const float* __restrict__ kb) {
    __shared__ __align__(16) float Ws[8][64];
    __shared__ __align__(16) float Xs[8][128];
    __shared__ float qk[64][129];
    __shared__ float part[32][8];
    const int t  = threadIdx.x;
    const int tx = t & 15, ty = t >> 4;       // n = tx*8, m = ty*4
    const int n0 = blockIdx.x * 128;
    const int b  = blockIdx.y;

    float acc[4][8];
    #pragma unroll
    for (int i = 0; i < 4; i++)
        #pragma unroll
        for (int j = 0; j < 8; j++) acc[i][j] = 0.f;

    const int w_m = t >> 2;
    const int w_k = (t & 3) * 2;
    const int x_k = t >> 5;
    const int x_n = (t & 31) * 4;
    const float* wrow = (w_m < 32) ? (qw + (size_t)w_m * CC) : (kw + (size_t)(w_m - 32) * CC);
    const float* fb = g_feat + (size_t)b * CC * HW;

    for (int k0 = 0; k0 < CC; k0 += 8) {
        float2 wv = *(const float2*)&wrow[k0 + w_k];
        Ws[w_k][w_m] = wv.x; Ws[w_k + 1][w_m] = wv.y;
        *(float4*)&Xs[x_k][x_n] = *(const float4*)&fb[(size_t)(k0 + x_k) * HW + n0 + x_n];
        __syncthreads();
        #pragma unroll
        for (int kk = 0; kk < 8; kk++) {
            float4 w  = *(float4*)&Ws[kk][ty * 4];
            float4 x0 = *(float4*)&Xs[kk][tx * 8];
            float4 x1 = *(float4*)&Xs[kk][tx * 8 + 4];
            float wr[4] = {w.x, w.y, w.z, w.w};
            float xr[8] = {x0.x, x0.y, x0.z, x0.w, x1.x, x1.y, x1.z, x1.w};
            #pragma unroll
            for (int i = 0; i < 4; i++)
                #pragma unroll
                for (int j = 0; j < 8; j++)
                    acc[i][j] = fmaf(wr[i], xr[j], acc[i][j]);
        }
        __syncthreads();
    }

    #pragma unroll
    for (int mi = 0; mi < 4; mi++) {
        int m = ty * 4 + mi;
        float bias = (m < 32) ? qb[m] : kb[m - 32];
        #pragma unroll
        for (int j = 0; j < 8; j++) qk[m][tx * 8 + j] = acc[mi][j] + bias;
    }
    __syncthreads();

    {   // per-pixel L2 normalize (h=0 -> Q, h=1 -> K)
        int n = t & 127, h = t >> 7;
        float ss = 0.f;
        #pragma unroll
        for (int m = 0; m < 32; m++) { float v = qk[h * 32 + m][n]; ss = fmaf(v, v, ss); }
        float inv = rsqrtf(ss);
        float* gout = (h == 0) ? g_Qn : g_Kn;
        size_t base = (size_t)b * CQ * HW + n0 + n;
        #pragma unroll
        for (int m = 0; m < 32; m++) {
            float v = qk[h * 32 + m][n] * inv;
            qk[h * 32 + m][n] = v;
            gout[base + (size_t)m * HW] = v;
        }
    }
    __syncthreads();
    {   // knsum partial
        int m = t >> 3, seg = t & 7;
        float s = 0.f;
        #pragma unroll
        for (int j = 0; j < 16; j++) s += qk[32 + m][seg * 16 + j];
        part[m][seg] = s;
    }
    __syncthreads();
    if (t < 32) {
        float s = 0.f;
        #pragma unroll
        for (int j = 0; j < 8; j++) s += part[t][j];
        atomicAdd(&g_knsum[b * CQ + t], s);
    }
}

// ---------------------------------------------------------------
// K3: G[b][m][c] = Σ_n Kn[b][m][n] * feat[b][c][n]  (split-K over n)
// ---------------------------------------------------------------
__global__ __launch_bounds__(256) void k_G() {
    __shared__ __align__(16) float Kns[32][36];
    __shared__ __align__(16) float fsT[32][256];
    const int t  = threadIdx.x;
    const int tx = t & 31, ty = t >> 5;      // c = tx*8, m = ty*4
    const int b  = blockIdx.y;
    const int nchunk0 = blockIdx.x * 576;

    float acc[4][8];
    #pragma unroll
    for (int i = 0; i < 4; i++)
        #pragma unroll
        for (int j = 0; j < 8; j++) acc[i][j] = 0.f;

    const int km = t >> 3;
    const int kn = (t & 7) * 4;
    const float* Knb = g_Kn + (size_t)b * CQ * HW;
    const float* fb  = g_feat + (size_t)b * CC * HW;

    for (int s = 0; s < 18; s++) {
        int nb = nchunk0 + s * 32;
        float4 kv = *(const float4*)&Knb[(size_t)km * HW + nb + kn];
        Kns[kn + 0][km] = kv.x; Kns[kn + 1][km] = kv.y;
        Kns[kn + 2][km] = kv.z; Kns[kn + 3][km] = kv.w;
        const float* fr = fb + (size_t)t * HW + nb;
        #pragma unroll
        for (int j = 0; j < 8; j++) {
            float4 fv = *(const float4*)&fr[j * 4];
            fsT[j * 4 + 0][t] = fv.x; fsT[j * 4 + 1][t] = fv.y;
            fsT[j * 4 + 2][t] = fv.z; fsT[j * 4 + 3][t] = fv.w;
        }
        __syncthreads();
        #pragma unroll
        for (int n = 0; n < 32; n++) {
            float4 k4 = *(float4*)&Kns[n][ty * 4];
            float4 f0 = *(float4*)&fsT[n][tx * 8];
            float4 f1 = *(float4*)&fsT[n][tx * 8 + 4];
            float kr[4] = {k4.x, k4.y, k4.z, k4.w};
            float fr8[8] = {f0.x, f0.y, f0.z, f0.w, f1.x, f1.y, f1.z, f1.w};
            #pragma unroll
            for (int i = 0; i < 4; i++)
                #pragma unroll
                for (int j = 0; j < 8; j++)
                    acc[i][j] = fmaf(kr[i], fr8[j], acc[i][j]);
        }
        __syncthreads();
    }
    #pragma unroll
    for (int i = 0; i < 4; i++)
        #pragma unroll
        for (int j = 0; j < 8; j++)
            atomicAdd(&g_G[((size_t)b * CQ + ty * 4 + i) * CC + tx * 8 + j], acc[i][j]);
}

// ---------------------------------------------------------------
// K4: matrix = G @ v_w^T + v_b ⊗ knsum ;  vsum = v_w @ fsum + N*v_b
// ---------------------------------------------------------------
__global__ __launch_bounds__(256) void k_matrix(const float* __restrict__ vw, const float* __restrict__ vb) {
    __shared__ __align__(16) float GsT[32][36];
    __shared__ __align__(16) float vwTs[32][256];
    __shared__ float fsums[256];
    const int t  = threadIdx.x;
    const int b  = blockIdx.x;
    const int tx = t & 31, ty = t >> 5;      // c = tx*8, m = ty*4

    float acc[4][8];
    #pragma unroll
    for (int i = 0; i < 4; i++)
        #pragma unroll
        for (int j = 0; j < 8; j++) acc[i][j] = 0.f;
    float vs = 0.f;

    fsums[t] = g_fsum[b * CC + t];
    const int gm = t & 31;
    const int gc = (t >> 5) * 4;

    for (int c0 = 0; c0 < CC; c0 += 32) {
        float4 gv = *(const float4*)&g_G[((size_t)b * CQ + gm) * CC + c0 + gc];
        GsT[gc + 0][gm] = gv.x; GsT[gc + 1][gm] = gv.y;
        GsT[gc + 2][gm] = gv.z; GsT[gc + 3][gm] = gv.w;
        const float* vr = vw + (size_t)t * CC + c0;
        #pragma unroll
        for (int j = 0; j < 8; j++) {
            float4 vv = *(const float4*)&vr[j * 4];
            vwTs[j * 4 + 0][t] = vv.x; vwTs[j * 4 + 1][t] = vv.y;
            vwTs[j * 4 + 2][t] = vv.z; vwTs[j * 4 + 3][t] = vv.w;
        }
        __syncthreads();
        #pragma unroll
        for (int cl = 0; cl < 32; cl++) {
            float4 g4 = *(float4*)&GsT[cl][ty * 4];
            float4 v0 = *(float4*)&vwTs[cl][tx * 8];
            float4 v1 = *(float4*)&vwTs[cl][tx * 8 + 4];
            float gr[4] = {g4.x, g4.y, g4.z, g4.w};
            float vr8[8] = {v0.x, v0.y, v0.z, v0.w, v1.x, v1.y, v1.z, v1.w};
            #pragma unroll
            for (int i = 0; i < 4; i++)
                #pragma unroll
                for (int j = 0; j < 8; j++)
                    acc[i][j] = fmaf(gr[i], vr8[j], acc[i][j]);
            vs = fmaf(vwTs[cl][t], fsums[c0 + cl], vs);
        }
        __syncthreads();
    }
    float kn[4];
    #pragma unroll
    for (int i = 0; i < 4; i++) kn[i] = g_knsum[b * CQ + ty * 4 + i];
    #pragma unroll
    for (int i = 0; i < 4; i++)
        #pragma unroll
        for (int j = 0; j < 8; j++) {
            int c = tx * 8 + j;
            g_matrix[((size_t)b * CQ + ty * 4 + i) * CC + c] = acc[i][j] + vb[c] * kn[i];
        }
    g_vsum[b * CC + t] = vs + NPIXF * vb[t];
}

// ---------------------------------------------------------------
// K5: per pixel: ms = matrix^T @ Qn + vsum ; tailor ; fused epilogue
//     out = feat*(feat + gamma*ms*tailor) + feat
// ---------------------------------------------------------------
__global__ __launch_bounds__(256) void k_final(const float* __restrict__ gamma, float* __restrict__ out) {
    __shared__ __align__(16) float ms[32][256];
    __shared__ __align__(16) float Qns[32][64];
    __shared__ float tails[64];
    __shared__ float vsums[256];
    __shared__ float kse[32];
    const int t  = threadIdx.x;
    const int tx = t & 7, ty = t >> 3;       // n = tx*8, c = ty*8
    const int n0 = blockIdx.x * 64;
    const int b  = blockIdx.y;

    {
        const float* mp = g_matrix + (size_t)b * CQ * CC;
        float* msf = &ms[0][0];
        #pragma unroll
        for (int j = 0; j < 8; j++) {
            int idx = t * 32 + j * 4;
            *(float4*)&msf[idx] = *(const float4*)&mp[idx];
        }
    }
    {
        int m = t >> 3, nl = (t & 7) * 8;
        const float* qp = g_Qn + ((size_t)b * CQ + m) * HW + n0 + nl;
        *(float4*)&Qns[m][nl]     = *(const float4*)&qp[0];
        *(float4*)&Qns[m][nl + 4] = *(const float4*)&qp[4];
    }
    vsums[t] = g_vsum[b * CC + t];
    if (t < 32) kse[t] = g_knsum[b * CQ + t] + 1e-6f;
    __syncthreads();
    if (t < 64) {
        float s = 0.f;
        #pragma unroll
        for (int m = 0; m < 32; m++) s = fmaf(Qns[m][t], kse[m], s);
        tails[t] = 1.0f / (NPIXF + s);
    }
    __syncthreads();

    float acc[8][8];
    #pragma unroll
    for (int i = 0; i < 8; i++)
        #pragma unroll
        for (int j = 0; j < 8; j++) acc[i][j] = 0.f;

    #pragma unroll 4
    for (int k = 0; k < 32; k++) {
        float4 m0v = *(float4*)&ms[k][ty * 8];
        float4 m1v = *(float4*)&ms[k][ty * 8 + 4];
        float4 q0  = *(float4*)&Qns[k][tx * 8];
        float4 q1  = *(float4*)&Qns[k][tx * 8 + 4];
        float mr[8] = {m0v.x, m0v.y, m0v.z, m0v.w, m1v.x, m1v.y, m1v.z, m1v.w};
        float qr[8] = {q0.x, q0.y, q0.z, q0.w, q1.x, q1.y, q1.z, q1.w};
        #pragma unroll
        for (int i = 0; i < 8; i++)
            #pragma unroll
            for (int j = 0; j < 8; j++)
                acc[i][j] = fmaf(mr[i], qr[j], acc[i][j]);
    }

    float gw = gamma[0];
    #pragma unroll
    for (int i = 0; i < 8; i++) {
        int c = ty * 8 + i;
        float vsc = vsums[c];
        size_t base = ((size_t)b * CC + c) * HW + n0 + tx * 8;
        float4 f0 = *(const float4*)&g_feat[base];
        float4 f1 = *(const float4*)&g_feat[base + 4];
        float fv[8] = {f0.x, f0.y, f0.z, f0.w, f1.x, f1.y, f1.z, f1.w};
        float o[8];
        #pragma unroll
        for (int j = 0; j < 8; j++) {
            float msv = acc[i][j] + vsc;
            float wv  = msv * tails[tx * 8 + j];
            float f   = fv[j];
            o[j] = fmaf(f, fmaf(gw, wv, f), f);   // f*(f + g*wv) + f
        }
        float4 s0 = {o[0], o[1], o[2], o[3]};
        float4 s1 = {o[4], o[5], o[6], o[7]};
        *(float4*)&out[base]     = s0;
        *(float4*)&out[base + 4] = s1;
    }
}

// ---------------------------------------------------------------
extern "C" void kernel_launch(void* const* d_in, const int* in_sizes, int n_in,
                              void* d_out, int out_size) {
    const float* fsp      = (const float*)d_in[0];
    const float* fcp      = (const float*)d_in[1];
    const float* conv_w   = (const float*)d_in[2];
    const float* bn_scale = (const float*)d_in[3];
    const float* bn_bias  = (const float*)d_in[4];
    const float* bn_mean  = (const float*)d_in[5];
    const float* bn_var   = (const float*)d_in[6];
    const float* gamma    = (const float*)d_in[7];
    const float* q_w      = (const float*)d_in[8];
    const float* q_b      = (const float*)d_in[9];
    const float* k_w      = (const float*)d_in[10];
    const float* k_b      = (const float*)d_in[11];
    const float* v_w      = (const float*)d_in[12];
    const float* v_b      = (const float*)d_in[13];
    float* out = (float*)d_out;

    k_setup<<<128, 256>>>(bn_scale, bn_bias, bn_mean, bn_var);
    k_conv  <<<dim3(72, 2, 16), 256>>>(fsp, fcp, conv_w);
    k_qk    <<<dim3(72, 16),    256>>>(q_w, q_b, k_w, k_b);
    k_G     <<<dim3(16, 16),    256>>>();
    k_matrix<<<16,              256>>>(v_w, v_b);
    k_final <<<dim3(144, 16),   256>>>(gamma, out);
}

// round 8
// speedup vs baseline: 1.5014x; 1.4940x over previous
#include <cuda_runtime.h>
#include <cuda_bf16.h>
#include <cstdint>

#define BB   16
#define CC   256
#define CHALF 128
#define CQ   32
#define HW   9216
#define NPIXF 9216.0f

// ---- scratch (device globals; no runtime allocation allowed) ----
__device__ __align__(256) float g_feat[(size_t)BB*CC*HW];
__device__ __align__(256) float g_Qn [(size_t)BB*CQ*HW];
__device__ __align__(256) float g_Kn [(size_t)BB*CQ*HW];
__device__ __align__(256) __nv_bfloat16 g_whiT[CC*CC];   // W^T hi  [k][m]
__device__ __align__(256) __nv_bfloat16 g_wloT[CC*CC];   // W^T lo  [k][m]
__device__ float g_G  [BB*CQ*CC];
__device__ float g_matrix[BB*CQ*CC];
__device__ float g_fsum[BB*CC];
__device__ float g_knsum[BB*CQ];
__device__ float g_vsum[BB*CC];
__device__ float g_bn_a[CC];
__device__ float g_bn_b[CC];

// =================== PTX helpers (sm_80-era, legal on sm_103 PTX) ===================
__device__ __forceinline__ uint32_t smem_u32(const void* p) {
    uint32_t a;
    asm("{ .reg .u64 t; cvta.to.shared.u64 t, %1; cvt.u32.u64 %0, t; }" : "=r"(a) : "l"(p));
    return a;
}
#define CP_ASYNC16(dst, src) \
    asm volatile("cp.async.cg.shared.global [%0], [%1], 16;" :: "r"(dst), "l"(src) : "memory")
#define CP_COMMIT() asm volatile("cp.async.commit_group;" ::: "memory")
#define CP_WAIT(n)  asm volatile("cp.async.wait_group %0;" :: "n"(n) : "memory")

#define LDSM_X4_T(r0, r1, r2, r3, addr) \
    asm volatile("ldmatrix.sync.aligned.m8n8.x4.trans.shared.b16 {%0,%1,%2,%3}, [%4];" \
                 : "=r"(r0), "=r"(r1), "=r"(r2), "=r"(r3) : "r"(addr))

#define MMA16816(d, a, b) \
    asm volatile("mma.sync.aligned.m16n8k16.row.col.f32.bf16.bf16.f32 " \
                 "{%0,%1,%2,%3}, {%4,%5,%6,%7}, {%8,%9}, {%0,%1,%2,%3};" \
                 : "+f"((d)[0]), "+f"((d)[1]), "+f"((d)[2]), "+f"((d)[3]) \
                 : "r"((a)[0]), "r"((a)[1]), "r"((a)[2]), "r"((a)[3]), \
                   "r"((b)[0]), "r"((b)[1]))

// ---------------------------------------------------------------
// K0: zero accumulators, fold BN, build W^T bf16 hi/lo
// ---------------------------------------------------------------
__global__ void k_setup(const float* __restrict__ bn_scale, const float* __restrict__ bn_bias,
                        const float* __restrict__ bn_mean,  const float* __restrict__ bn_var,
                        const float* __restrict__ conv_w) {
    int t = blockIdx.x * blockDim.x + threadIdx.x;
    int stride = gridDim.x * blockDim.x;
    for (int i = t; i < BB*CQ*CC; i += stride) g_G[i] = 0.f;
    for (int i = t; i < BB*CC;    i += stride) g_fsum[i] = 0.f;
    for (int i = t; i < BB*CQ;    i += stride) g_knsum[i] = 0.f;
    for (int i = t; i < CC*CC;    i += stride) {
        int k = i >> 8, m = i & 255;              // i = k*256 + m
        float w = conv_w[m * CC + k];
        __nv_bfloat16 hi = __float2bfloat16(w);
        g_whiT[i] = hi;
        g_wloT[i] = __float2bfloat16(w - __bfloat162float(hi));
    }
    if (t < CC) {
        float inv = rsqrtf(bn_var[t] + 1e-5f);
        float a = bn_scale[t] * inv;
        g_bn_a[t] = a;
        g_bn_b[t] = bn_bias[t] - bn_mean[t] * a;
    }
}

// ---------------------------------------------------------------
// K1: conv1x1 + BN + ReLU via mma.sync bf16 (3-term split)
//     BM=256 (full M), BN=128, BK=32; 512 threads = 16 warps (64x32 each)
//     A = W^T hi/lo via cp.async (double buffered, swizzled, ldmatrix.trans)
//     B = X fp32 from fsp/fcp -> reg convert -> STS hi/lo (double buffered)
// SMEM: A [2 stg][2 h][32 k][512B] = 64KB ; B at +65536 [2 stg][2 h][32 k][256B] = 32KB
// ---------------------------------------------------------------
#define CONV_SMEM 98304
__global__ __launch_bounds__(512, 1) void k_conv_mma(const float* __restrict__ fsp,
                                                     const float* __restrict__ fcp) {
    extern __shared__ __align__(128) char smem[];
    const uint32_t smemb = smem_u32(smem);
    const int t    = threadIdx.x;
    const int lane = t & 31;
    const int wid  = t >> 5;
    const int n0   = blockIdx.x * 128;
    const int b    = blockIdx.y;
    const int wm   = (wid >> 2) * 64;     // warp M offset (0..192)
    const int wn   = (wid & 3) * 32;      // warp N offset (0..96)

    float acc[4][4][4];
    #pragma unroll
    for (int i = 0; i < 4; i++)
        #pragma unroll
        for (int j = 0; j < 4; j++)
            #pragma unroll
            for (int q = 0; q < 4; q++) acc[i][j][q] = 0.f;

    // ---- X prefetch (per thread: row xr of 32, 8 consecutive floats) ----
    const int xr = t >> 4;
    const int xc = (t & 15) * 8;
    float4 X0, X1;
    {
        int cg = xr;  // kc = 0
        const float* p = (cg < CHALF ? fsp + ((size_t)b * CHALF + cg) * HW
                                     : fcp + ((size_t)b * CHALF + cg - CHALF) * HW) + n0 + xc;
        X0 = *(const float4*)p; X1 = *(const float4*)(p + 4);
    }

    // ---- A chunk loader (cp.async, commits one group) ----
    auto loadA = [&](int kc, int s) {
        #pragma unroll
        for (int p = 0; p < 4; p++) {
            int idx = t + p * 512;
            int h = idx >> 10, rem = idx & 1023;
            int r = rem >> 5, c = rem & 31;
            const __nv_bfloat16* src =
                (h ? g_wloT : g_whiT) + (size_t)(kc * 32 + r) * CC + c * 8;
            uint32_t dst = smemb + s * 32768 + h * 16384 + r * 512 + ((c ^ (r & 7)) << 4);
            CP_ASYNC16(dst, src);
        }
        CP_COMMIT();
    };

    loadA(0, 0);

    for (int kc = 0; kc < 8; kc++) {
        const int s = kc & 1;
        // STS B chunk kc (convert fp32 -> bf16 hi/lo)
        {
            float xv[8] = {X0.x, X0.y, X0.z, X0.w, X1.x, X1.y, X1.z, X1.w};
            __align__(16) __nv_bfloat16 hi[8], lo[8];
            #pragma unroll
            for (int q = 0; q < 8; q++) {
                hi[q] = __float2bfloat16(xv[q]);
                lo[q] = __float2bfloat16(xv[q] - __bfloat162float(hi[q]));
            }
            int c = t & 15;
            uint32_t off = 65536 + s * 16384 + xr * 256 + ((c ^ (xr & 7)) << 4);
            *(uint4*)(smem + off)        = *(uint4*)hi;
            *(uint4*)(smem + off + 8192) = *(uint4*)lo;
        }
        if (kc < 7) { loadA(kc + 1, s ^ 1); CP_WAIT(1); }
        else        { CP_WAIT(0); }
        __syncthreads();

        // prefetch next X chunk into regs (overlaps MMA below)
        if (kc < 7) {
            int cg = (kc + 1) * 32 + xr;
            const float* p = (cg < CHALF ? fsp + ((size_t)b * CHALF + cg) * HW
                                         : fcp + ((size_t)b * CHALF + cg - CHALF) * HW) + n0 + xc;
            X0 = *(const float4*)p; X1 = *(const float4*)(p + 4);
        }

        // ---- compute chunk (K=32 -> two k16 halves) ----
        const int l = lane & 7, g = lane >> 3;
        #pragma unroll
        for (int ks8 = 0; ks8 < 2; ks8++) {
            const int ks = ks8 * 16;
            uint32_t Bh[4][2], Bl[4][2];
            #pragma unroll
            for (int h = 0; h < 2; h++)
                #pragma unroll
                for (int jp = 0; jp < 2; jp++) {
                    int r = ks + ((g & 1) << 3) + l;
                    int c = (wn >> 3) + jp * 2 + (g >> 1);
                    uint32_t ad = smemb + 65536 + s * 16384 + h * 8192
                                + r * 256 + ((c ^ (r & 7)) << 4);
                    uint32_t q0, q1, q2, q3;
                    LDSM_X4_T(q0, q1, q2, q3, ad);
                    if (h == 0) { Bh[jp*2][0]=q0; Bh[jp*2][1]=q1; Bh[jp*2+1][0]=q2; Bh[jp*2+1][1]=q3; }
                    else        { Bl[jp*2][0]=q0; Bl[jp*2][1]=q1; Bl[jp*2+1][0]=q2; Bl[jp*2+1][1]=q3; }
                }
            #pragma unroll
            for (int i = 0; i < 4; i++) {
                uint32_t Ah[4], Al[4];
                {
                    int r = ks + ((g >> 1) << 3) + l;
                    int c = ((wm + i * 16) >> 3) + (g & 1);
                    uint32_t boff = r * 512 + ((c ^ (r & 7)) << 4);
                    LDSM_X4_T(Ah[0], Ah[1], Ah[2], Ah[3], smemb + s * 32768 + boff);
                    LDSM_X4_T(Al[0], Al[1], Al[2], Al[3], smemb + s * 32768 + 16384 + boff);
                }
                #pragma unroll
                for (int j = 0; j < 4; j++) {
                    MMA16816(acc[i][j], Ah, Bh[j]);
                    MMA16816(acc[i][j], Ah, Bl[j]);
                    MMA16816(acc[i][j], Al, Bh[j]);
                }
            }
        }
        // trailing barrier: orders this iter's smem READS before next iter's
        // cp.async/STS WRITES into the opposite (and later the same) stage.
        __syncthreads();
    }

    // ---- epilogue: BN + ReLU, store feat, fsum via quad reduce + atomics ----
    #pragma unroll
    for (int i = 0; i < 4; i++) {
        int mlo = wm + i * 16 + (lane >> 2);
        int mhi = mlo + 8;
        float a0 = g_bn_a[mlo], c0 = g_bn_b[mlo];
        float a1 = g_bn_a[mhi], c1 = g_bn_b[mhi];
        float rs0 = 0.f, rs1 = 0.f;
        float* f_lo = g_feat + ((size_t)b * CC + mlo) * HW;
        float* f_hi = g_feat + ((size_t)b * CC + mhi) * HW;
        #pragma unroll
        for (int j = 0; j < 4; j++) {
            int n = n0 + wn + j * 8 + (lane & 3) * 2;
            float y00 = fmaxf(fmaf(acc[i][j][0], a0, c0), 0.f);
            float y01 = fmaxf(fmaf(acc[i][j][1], a0, c0), 0.f);
            float y10 = fmaxf(fmaf(acc[i][j][2], a1, c1), 0.f);
            float y11 = fmaxf(fmaf(acc[i][j][3], a1, c1), 0.f);
            float2 s0 = {y00, y01}; float2 s1 = {y10, y11};
            *(float2*)&f_lo[n] = s0;
            *(float2*)&f_hi[n] = s1;
            rs0 += y00 + y01; rs1 += y10 + y11;
        }
        rs0 += __shfl_xor_sync(0xFFFFFFFF, rs0, 1);
        rs0 += __shfl_xor_sync(0xFFFFFFFF, rs0, 2);
        rs1 += __shfl_xor_sync(0xFFFFFFFF, rs1, 1);
        rs1 += __shfl_xor_sync(0xFFFFFFFF, rs1, 2);
        if ((lane & 3) == 0) {
            atomicAdd(&g_fsum[b * CC + mlo], rs0);
            atomicAdd(&g_fsum[b * CC + mhi], rs1);
        }
    }
}

// ---------------------------------------------------------------
// K2: QK = [q_w;k_w] @ feat (+bias), per-pixel L2 norm, knsum
// ---------------------------------------------------------------
__global__ __launch_bounds__(256) void k_qk(const float* __restrict__ qw, const float* __restrict__ qb,
                                            const float* __restrict__ kw, const float* __restrict__ kb) {
    __shared__ __align__(16) float Ws[8][64];
    __shared__ __align__(16) float Xs[8][128];
    __shared__ float qk[64][129];
    __shared__ float part[32][8];
    const int t  = threadIdx.x;
    const int tx = t & 15, ty = t >> 4;
    const int n0 = blockIdx.x * 128;
    const int b  = blockIdx.y;

    float acc[4][8];
    #pragma unroll
    for (int i = 0; i < 4; i++)
        #pragma unroll
        for (int j = 0; j < 8; j++) acc[i][j] = 0.f;

    const int w_m = t >> 2;
    const int w_k = (t & 3) * 2;
    const int x_k = t >> 5;
    const int x_n = (t & 31) * 4;
    const float* wrow = (w_m < 32) ? (qw + (size_t)w_m * CC) : (kw + (size_t)(w_m - 32) * CC);
    const float* fb = g_feat + (size_t)b * CC * HW;

    for (int k0 = 0; k0 < CC; k0 += 8) {
        float2 wv = *(const float2*)&wrow[k0 + w_k];
        Ws[w_k][w_m] = wv.x; Ws[w_k + 1][w_m] = wv.y;
        *(float4*)&Xs[x_k][x_n] = *(const float4*)&fb[(size_t)(k0 + x_k) * HW + n0 + x_n];
        __syncthreads();
        #pragma unroll
        for (int kk = 0; kk < 8; kk++) {
            float4 w  = *(float4*)&Ws[kk][ty * 4];
            float4 x0 = *(float4*)&Xs[kk][tx * 8];
            float4 x1 = *(float4*)&Xs[kk][tx * 8 + 4];
            float wr[4] = {w.x, w.y, w.z, w.w};
            float xr[8] = {x0.x, x0.y, x0.z, x0.w, x1.x, x1.y, x1.z, x1.w};
            #pragma unroll
            for (int i = 0; i < 4; i++)
                #pragma unroll
                for (int j = 0; j < 8; j++)
                    acc[i][j] = fmaf(wr[i], xr[j], acc[i][j]);
        }
        __syncthreads();
    }

    #pragma unroll
    for (int mi = 0; mi < 4; mi++) {
        int m = ty * 4 + mi;
        float bias = (m < 32) ? qb[m] : kb[m - 32];
        #pragma unroll
        for (int j = 0; j < 8; j++) qk[m][tx * 8 + j] = acc[mi][j] + bias;
    }
    __syncthreads();

    {
        int n = t & 127, h = t >> 7;
        float ss = 0.f;
        #pragma unroll
        for (int m = 0; m < 32; m++) { float v = qk[h * 32 + m][n]; ss = fmaf(v, v, ss); }
        float inv = rsqrtf(ss);
        float* gout = (h == 0) ? g_Qn : g_Kn;
        size_t base = (size_t)b * CQ * HW + n0 + n;
        #pragma unroll
        for (int m = 0; m < 32; m++) {
            float v = qk[h * 32 + m][n] * inv;
            qk[h * 32 + m][n] = v;
            gout[base + (size_t)m * HW] = v;
        }
    }
    __syncthreads();
    {
        int m = t >> 3, seg = t & 7;
        float s = 0.f;
        #pragma unroll
        for (int j = 0; j < 16; j++) s += qk[32 + m][seg * 16 + j];
        part[m][seg] = s;
    }
    __syncthreads();
    if (t < 32) {
        float s = 0.f;
        #pragma unroll
        for (int j = 0; j < 8; j++) s += part[t][j];
        atomicAdd(&g_knsum[b * CQ + t], s);
    }
}

// ---------------------------------------------------------------
// K3: G[b][m][c] = sum_n Kn[b][m][n] * feat[b][c][n]
// ---------------------------------------------------------------
__global__ __launch_bounds__(256) void k_G() {
    __shared__ __align__(16) float Kns[32][36];
    __shared__ __align__(16) float fsT[32][256];
    const int t  = threadIdx.x;
    const int tx = t & 31, ty = t >> 5;
    const int b  = blockIdx.y;
    const int nchunk0 = blockIdx.x * 576;

    float acc[4][8];
    #pragma unroll
    for (int i = 0; i < 4; i++)
        #pragma unroll
        for (int j = 0; j < 8; j++) acc[i][j] = 0.f;

    const int km = t >> 3;
    const int kn = (t & 7) * 4;
    const float* Knb = g_Kn + (size_t)b * CQ * HW;
    const float* fb  = g_feat + (size_t)b * CC * HW;

    for (int s = 0; s < 18; s++) {
        int nb = nchunk0 + s * 32;
        float4 kv = *(const float4*)&Knb[(size_t)km * HW + nb + kn];
        Kns[kn + 0][km] = kv.x; Kns[kn + 1][km] = kv.y;
        Kns[kn + 2][km] = kv.z; Kns[kn + 3][km] = kv.w;
        const float* fr = fb + (size_t)t * HW + nb;
        #pragma unroll
        for (int j = 0; j < 8; j++) {
            float4 fv = *(const float4*)&fr[j * 4];
            fsT[j * 4 + 0][t] = fv.x; fsT[j * 4 + 1][t] = fv.y;
            fsT[j * 4 + 2][t] = fv.z; fsT[j * 4 + 3][t] = fv.w;
        }
        __syncthreads();
        #pragma unroll
        for (int n = 0; n < 32; n++) {
            float4 k4 = *(float4*)&Kns[n][ty * 4];
            float4 f0 = *(float4*)&fsT[n][tx * 8];
            float4 f1 = *(float4*)&fsT[n][tx * 8 + 4];
            float kr[4] = {k4.x, k4.y, k4.z, k4.w};
            float fr8[8] = {f0.x, f0.y, f0.z, f0.w, f1.x, f1.y, f1.z, f1.w};
            #pragma unroll
            for (int i = 0; i < 4; i++)
                #pragma unroll
                for (int j = 0; j < 8; j++)
                    acc[i][j] = fmaf(kr[i], fr8[j], acc[i][j]);
        }
        __syncthreads();
    }
    #pragma unroll
    for (int i = 0; i < 4; i++)
        #pragma unroll
        for (int j = 0; j < 8; j++)
            atomicAdd(&g_G[((size_t)b * CQ + ty * 4 + i) * CC + tx * 8 + j], acc[i][j]);
}

// ---------------------------------------------------------------
// K4: matrix = G @ v_w^T + v_b x knsum ; vsum = v_w @ fsum + N*v_b
// ---------------------------------------------------------------
__global__ __launch_bounds__(256) void k_matrix(const float* __restrict__ vw, const float* __restrict__ vb) {
    __shared__ __align__(16) float GsT[32][36];
    __shared__ __align__(16) float vwTs[32][256];
    __shared__ float fsums[256];
    const int t  = threadIdx.x;
    const int b  = blockIdx.x;
    const int tx = t & 31, ty = t >> 5;

    float acc[4][8];
    #pragma unroll
    for (int i = 0; i < 4; i++)
        #pragma unroll
        for (int j = 0; j < 8; j++) acc[i][j] = 0.f;
    float vs = 0.f;

    fsums[t] = g_fsum[b * CC + t];
    const int gm = t & 31;
    const int gc = (t >> 5) * 4;

    for (int c0 = 0; c0 < CC; c0 += 32) {
        float4 gv = *(const float4*)&g_G[((size_t)b * CQ + gm) * CC + c0 + gc];
        GsT[gc + 0][gm] = gv.x; GsT[gc + 1][gm] = gv.y;
        GsT[gc + 2][gm] = gv.z; GsT[gc + 3][gm] = gv.w;
        const float* vr = vw + (size_t)t * CC + c0;
        #pragma unroll
        for (int j = 0; j < 8; j++) {
            float4 vv = *(const float4*)&vr[j * 4];
            vwTs[j * 4 + 0][t] = vv.x; vwTs[j * 4 + 1][t] = vv.y;
            vwTs[j * 4 + 2][t] = vv.z; vwTs[j * 4 + 3][t] = vv.w;
        }
        __syncthreads();
        #pragma unroll
        for (int cl = 0; cl < 32; cl++) {
            float4 g4 = *(float4*)&GsT[cl][ty * 4];
            float4 v0 = *(float4*)&vwTs[cl][tx * 8];
            float4 v1 = *(float4*)&vwTs[cl][tx * 8 + 4];
            float gr[4] = {g4.x, g4.y, g4.z, g4.w};
            float vr8[8] = {v0.x, v0.y, v0.z, v0.w, v1.x, v1.y, v1.z, v1.w};
            #pragma unroll
            for (int i = 0; i < 4; i++)
                #pragma unroll
                for (int j = 0; j < 8; j++)
                    acc[i][j] = fmaf(gr[i], vr8[j], acc[i][j]);
            vs = fmaf(vwTs[cl][t], fsums[c0 + cl], vs);
        }
        __syncthreads();
    }
    float kn[4];
    #pragma unroll
    for (int i = 0; i < 4; i++) kn[i] = g_knsum[b * CQ + ty * 4 + i];
    #pragma unroll
    for (int i = 0; i < 4; i++)
        #pragma unroll
        for (int j = 0; j < 8; j++) {
            int c = tx * 8 + j;
            g_matrix[((size_t)b * CQ + ty * 4 + i) * CC + c] = acc[i][j] + vb[c] * kn[i];
        }
    g_vsum[b * CC + t] = vs + NPIXF * vb[t];
}

// ---------------------------------------------------------------
// K5: per pixel: ms = matrix^T @ Qn + vsum ; tailor ; fused epilogue
// ---------------------------------------------------------------
__global__ __launch_bounds__(256) void k_final(const float* __restrict__ gamma, float* __restrict__ out) {
    __shared__ __align__(16) float ms[32][256];
    __shared__ __align__(16) float Qns[32][64];
    __shared__ float tails[64];
    __shared__ float vsums[256];
    __shared__ float kse[32];
    const int t  = threadIdx.x;
    const int tx = t & 7, ty = t >> 3;
    const int n0 = blockIdx.x * 64;
    const int b  = blockIdx.y;

    {
        const float* mp = g_matrix + (size_t)b * CQ * CC;
        float* msf = &ms[0][0];
        #pragma unroll
        for (int j = 0; j < 8; j++) {
            int idx = t * 32 + j * 4;
            *(float4*)&msf[idx] = *(const float4*)&mp[idx];
        }
    }
    {
        int m = t >> 3, nl = (t & 7) * 8;
        const float* qp = g_Qn + ((size_t)b * CQ + m) * HW + n0 + nl;
        *(float4*)&Qns[m][nl]     = *(const float4*)&qp[0];
        *(float4*)&Qns[m][nl + 4] = *(const float4*)&qp[4];
    }
    vsums[t] = g_vsum[b * CC + t];
    if (t < 32) kse[t] = g_knsum[b * CQ + t] + 1e-6f;
    __syncthreads();
    if (t < 64) {
        float s = 0.f;
        #pragma unroll
        for (int m = 0; m < 32; m++) s = fmaf(Qns[m][t], kse[m], s);
        tails[t] = 1.0f / (NPIXF + s);
    }
    __syncthreads();

    float acc[8][8];
    #pragma unroll
    for (int i = 0; i < 8; i++)
        #pragma unroll
        for (int j = 0; j < 8; j++) acc[i][j] = 0.f;

    #pragma unroll 4
    for (int k = 0; k < 32; k++) {
        float4 m0v = *(float4*)&ms[k][ty * 8];
        float4 m1v = *(float4*)&ms[k][ty * 8 + 4];
        float4 q0  = *(float4*)&Qns[k][tx * 8];
        float4 q1  = *(float4*)&Qns[k][tx * 8 + 4];
        float mr[8] = {m0v.x, m0v.y, m0v.z, m0v.w, m1v.x, m1v.y, m1v.z, m1v.w};
        float qr[8] = {q0.x, q0.y, q0.z, q0.w, q1.x, q1.y, q1.z, q1.w};
        #pragma unroll
        for (int i = 0; i < 8; i++)
            #pragma unroll
            for (int j = 0; j < 8; j++)
                acc[i][j] = fmaf(mr[i], qr[j], acc[i][j]);
    }

    float gw = gamma[0];
    #pragma unroll
    for (int i = 0; i < 8; i++) {
        int c = ty * 8 + i;
        float vsc = vsums[c];
        size_t base = ((size_t)b * CC + c) * HW + n0 + tx * 8;
        float4 f0 = *(const float4*)&g_feat[base];
        float4 f1 = *(const float4*)&g_feat[base + 4];
        float fv[8] = {f0.x, f0.y, f0.z, f0.w, f1.x, f1.y, f1.z, f1.w};
        float o[8];
        #pragma unroll
        for (int j = 0; j < 8; j++) {
            float msv = acc[i][j] + vsc;
            float wv  = msv * tails[tx * 8 + j];
            float f   = fv[j];
            o[j] = fmaf(f, fmaf(gw, wv, f), f);
        }
        float4 s0 = {o[0], o[1], o[2], o[3]};
        float4 s1 = {o[4], o[5], o[6], o[7]};
        *(float4*)&out[base]     = s0;
        *(float4*)&out[base + 4] = s1;
    }
}

// ---------------------------------------------------------------
extern "C" void kernel_launch(void* const* d_in, const int* in_sizes, int n_in,
                              void* d_out, int out_size) {
    const float* fsp      = (const float*)d_in[0];
    const float* fcp      = (const float*)d_in[1];
    const float* conv_w   = (const float*)d_in[2];
    const float* bn_scale = (const float*)d_in[3];
    const float* bn_bias  = (const float*)d_in[4];
    const float* bn_mean  = (const float*)d_in[5];
    const float* bn_var   = (const float*)d_in[6];
    const float* gamma    = (const float*)d_in[7];
    const float* q_w      = (const float*)d_in[8];
    const float* q_b      = (const float*)d_in[9];
    const float* k_w      = (const float*)d_in[10];
    const float* k_b      = (const float*)d_in[11];
    const float* v_w      = (const float*)d_in[12];
    const float* v_b      = (const float*)d_in[13];
    float* out = (float*)d_out;

    cudaFuncSetAttribute(k_conv_mma, cudaFuncAttributeMaxDynamicSharedMemorySize, CONV_SMEM);

    k_setup<<<128, 256>>>(bn_scale, bn_bias, bn_mean, bn_var, conv_w);
    k_conv_mma<<<dim3(72, 16), 512, CONV_SMEM>>>(fsp, fcp);
    k_qk    <<<dim3(72, 16), 256>>>(q_w, q_b, k_w, k_b);
    k_G     <<<dim3(16, 16), 256>>>();
    k_matrix<<<16,           256>>>(v_w, v_b);
    k_final <<<dim3(144, 16), 256>>>(gamma, out);
}

// round 10
// speedup vs baseline: 2.1728x; 1.4471x over previous
#include <cuda_runtime.h>
#include <cuda_bf16.h>
#include <cstdint>

#define BB   16
#define CC   256
#define CHALF 128
#define CQ   32
#define HW   9216
#define NPIXF 9216.0f

// ---- scratch (device globals; no runtime allocation allowed) ----
__device__ __align__(256) float g_feat[(size_t)BB*CC*HW];
__device__ __align__(256) __nv_bfloat16 g_fhi[(size_t)BB*CC*HW];
__device__ __align__(256) __nv_bfloat16 g_flo[(size_t)BB*CC*HW];
__device__ __align__(256) float g_Qn [(size_t)BB*CQ*HW];
__device__ __align__(256) __nv_bfloat16 g_knhi[(size_t)BB*CQ*HW];
__device__ __align__(256) __nv_bfloat16 g_knlo[(size_t)BB*CQ*HW];
__device__ __align__(256) __nv_bfloat16 g_whiT[CC*CC];    // W^T hi  [k][m]
__device__ __align__(256) __nv_bfloat16 g_wloT[CC*CC];    // W^T lo  [k][m]
__device__ __align__(256) __nv_bfloat16 g_qkwhi[CC*64];   // [c][m] m<32:q, else k
__device__ __align__(256) __nv_bfloat16 g_qkwlo[CC*64];
__device__ float g_G  [BB*CQ*CC];
__device__ float g_matrix[BB*CQ*CC];
__device__ float g_fsum[BB*CC];
__device__ float g_knsum[BB*CQ];
__device__ float g_vsum[BB*CC];
__device__ float g_bn_a[CC];
__device__ float g_bn_b[CC];

// =================== PTX helpers (sm_80-era, legal on sm_103 PTX) ===================
__device__ __forceinline__ uint32_t smem_u32(const void* p) {
    uint32_t a;
    asm("{ .reg .u64 t; cvta.to.shared.u64 t, %1; cvt.u32.u64 %0, t; }" : "=r"(a) : "l"(p));
    return a;
}
#define CP_ASYNC16(dst, src) \
    asm volatile("cp.async.cg.shared.global [%0], [%1], 16;" :: "r"(dst), "l"(src) : "memory")
#define CP_COMMIT() asm volatile("cp.async.commit_group;" ::: "memory")
#define CP_WAIT(n)  asm volatile("cp.async.wait_group %0;" :: "n"(n) : "memory")

#define LDSM_X4_T(r0, r1, r2, r3, addr) \
    asm volatile("ldmatrix.sync.aligned.m8n8.x4.trans.shared.b16 {%0,%1,%2,%3}, [%4];" \
                 : "=r"(r0), "=r"(r1), "=r"(r2), "=r"(r3) : "r"(addr))
#define LDSM_X4(r0, r1, r2, r3, addr) \
    asm volatile("ldmatrix.sync.aligned.m8n8.x4.shared.b16 {%0,%1,%2,%3}, [%4];" \
                 : "=r"(r0), "=r"(r1), "=r"(r2), "=r"(r3) : "r"(addr))

#define MMA16816(d, a, b) \
    asm volatile("mma.sync.aligned.m16n8k16.row.col.f32.bf16.bf16.f32 " \
                 "{%0,%1,%2,%3}, {%4,%5,%6,%7}, {%8,%9}, {%0,%1,%2,%3};" \
                 : "+f"((d)[0]), "+f"((d)[1]), "+f"((d)[2]), "+f"((d)[3]) \
                 : "r"((a)[0]), "r"((a)[1]), "r"((a)[2]), "r"((a)[3]), \
                   "r"((b)[0]), "r"((b)[1]))

// ---------------------------------------------------------------
// K0: zero accumulators, fold BN, build bf16 hi/lo weights
// ---------------------------------------------------------------
__global__ void k_setup(const float* __restrict__ bn_scale, const float* __restrict__ bn_bias,
                        const float* __restrict__ bn_mean,  const float* __restrict__ bn_var,
                        const float* __restrict__ conv_w,
                        const float* __restrict__ qw, const float* __restrict__ kw) {
    int t = blockIdx.x * blockDim.x + threadIdx.x;
    int stride = gridDim.x * blockDim.x;
    for (int i = t; i < BB*CQ*CC; i += stride) g_G[i] = 0.f;
    for (int i = t; i < BB*CC;    i += stride) g_fsum[i] = 0.f;
    for (int i = t; i < BB*CQ;    i += stride) g_knsum[i] = 0.f;
    for (int i = t; i < CC*CC;    i += stride) {
        int k = i >> 8, m = i & 255;
        float w = conv_w[m * CC + k];
        __nv_bfloat16 hi = __float2bfloat16(w);
        g_whiT[i] = hi;
        g_wloT[i] = __float2bfloat16(w - __bfloat162float(hi));
    }
    for (int i = t; i < CC*64; i += stride) {
        int c = i >> 6, mm = i & 63;
        float w = (mm < 32) ? qw[mm * CC + c] : kw[(mm - 32) * CC + c];
        __nv_bfloat16 hi = __float2bfloat16(w);
        g_qkwhi[i] = hi;
        g_qkwlo[i] = __float2bfloat16(w - __bfloat162float(hi));
    }
    if (t < CC) {
        float inv = rsqrtf(bn_var[t] + 1e-5f);
        float a = bn_scale[t] * inv;
        g_bn_a[t] = a;
        g_bn_b[t] = bn_bias[t] - bn_mean[t] * a;
    }
}

// ---------------------------------------------------------------
// K1: conv1x1 + BN + ReLU via mma.sync bf16 (3-term split)
//     also emits feat as bf16 hi/lo for downstream HMMA consumers
// ---------------------------------------------------------------
#define CONV_SMEM 98304
__global__ __launch_bounds__(512, 1) void k_conv_mma(const float* __restrict__ fsp,
                                                     const float* __restrict__ fcp) {
    extern __shared__ __align__(128) char smem[];
    const uint32_t smemb = smem_u32(smem);
    const int t    = threadIdx.x;
    const int lane = t & 31;
    const int wid  = t >> 5;
    const int n0   = blockIdx.x * 128;
    const int b    = blockIdx.y;
    const int wm   = (wid >> 2) * 64;
    const int wn   = (wid & 3) * 32;

    float acc[4][4][4];
    #pragma unroll
    for (int i = 0; i < 4; i++)
        #pragma unroll
        for (int j = 0; j < 4; j++)
            #pragma unroll
            for (int q = 0; q < 4; q++) acc[i][j][q] = 0.f;

    const int xr = t >> 4;
    const int xc = (t & 15) * 8;
    float4 X0, X1;
    {
        int cg = xr;
        const float* p = (cg < CHALF ? fsp + ((size_t)b * CHALF + cg) * HW
                                     : fcp + ((size_t)b * CHALF + cg - CHALF) * HW) + n0 + xc;
        X0 = *(const float4*)p; X1 = *(const float4*)(p + 4);
    }

    auto loadA = [&](int kc, int s) {
        #pragma unroll
        for (int p = 0; p < 4; p++) {
            int idx = t + p * 512;
            int h = idx >> 10, rem = idx & 1023;
            int r = rem >> 5, c = rem & 31;
            const __nv_bfloat16* src =
                (h ? g_wloT : g_whiT) + (size_t)(kc * 32 + r) * CC + c * 8;
            uint32_t dst = smemb + s * 32768 + h * 16384 + r * 512 + ((c ^ (r & 7)) << 4);
            CP_ASYNC16(dst, src);
        }
        CP_COMMIT();
    };

    loadA(0, 0);

    for (int kc = 0; kc < 8; kc++) {
        const int s = kc & 1;
        {
            float xv[8] = {X0.x, X0.y, X0.z, X0.w, X1.x, X1.y, X1.z, X1.w};
            __align__(16) __nv_bfloat16 hi[8], lo[8];
            #pragma unroll
            for (int q = 0; q < 8; q++) {
                hi[q] = __float2bfloat16(xv[q]);
                lo[q] = __float2bfloat16(xv[q] - __bfloat162float(hi[q]));
            }
            int c = t & 15;
            uint32_t off = 65536 + s * 16384 + xr * 256 + ((c ^ (xr & 7)) << 4);
            *(uint4*)(smem + off)        = *(uint4*)hi;
            *(uint4*)(smem + off + 8192) = *(uint4*)lo;
        }
        if (kc < 7) { loadA(kc + 1, s ^ 1); CP_WAIT(1); }
        else        { CP_WAIT(0); }
        __syncthreads();

        if (kc < 7) {
            int cg = (kc + 1) * 32 + xr;
            const float* p = (cg < CHALF ? fsp + ((size_t)b * CHALF + cg) * HW
                                         : fcp + ((size_t)b * CHALF + cg - CHALF) * HW) + n0 + xc;
            X0 = *(const float4*)p; X1 = *(const float4*)(p + 4);
        }

        const int l = lane & 7, g = lane >> 3;
        #pragma unroll
        for (int ks8 = 0; ks8 < 2; ks8++) {
            const int ks = ks8 * 16;
            uint32_t Bh[4][2], Bl[4][2];
            #pragma unroll
            for (int h = 0; h < 2; h++)
                #pragma unroll
                for (int jp = 0; jp < 2; jp++) {
                    int r = ks + ((g & 1) << 3) + l;
                    int c = (wn >> 3) + jp * 2 + (g >> 1);
                    uint32_t ad = smemb + 65536 + s * 16384 + h * 8192
                                + r * 256 + ((c ^ (r & 7)) << 4);
                    uint32_t q0, q1, q2, q3;
                    LDSM_X4_T(q0, q1, q2, q3, ad);
                    if (h == 0) { Bh[jp*2][0]=q0; Bh[jp*2][1]=q1; Bh[jp*2+1][0]=q2; Bh[jp*2+1][1]=q3; }
                    else        { Bl[jp*2][0]=q0; Bl[jp*2][1]=q1; Bl[jp*2+1][0]=q2; Bl[jp*2+1][1]=q3; }
                }
            #pragma unroll
            for (int i = 0; i < 4; i++) {
                uint32_t Ah[4], Al[4];
                {
                    int r = ks + ((g >> 1) << 3) + l;
                    int c = ((wm + i * 16) >> 3) + (g & 1);
                    uint32_t boff = r * 512 + ((c ^ (r & 7)) << 4);
                    LDSM_X4_T(Ah[0], Ah[1], Ah[2], Ah[3], smemb + s * 32768 + boff);
                    LDSM_X4_T(Al[0], Al[1], Al[2], Al[3], smemb + s * 32768 + 16384 + boff);
                }
                #pragma unroll
                for (int j = 0; j < 4; j++) {
                    MMA16816(acc[i][j], Ah, Bh[j]);
                    MMA16816(acc[i][j], Ah, Bl[j]);
                    MMA16816(acc[i][j], Al, Bh[j]);
                }
            }
        }
        __syncthreads();
    }

    // ---- epilogue: BN + ReLU, store feat fp32 + bf16 hi/lo, fsum ----
    #pragma unroll
    for (int i = 0; i < 4; i++) {
        int mlo = wm + i * 16 + (lane >> 2);
        int mhi = mlo + 8;
        float a0 = g_bn_a[mlo], c0 = g_bn_b[mlo];
        float a1 = g_bn_a[mhi], c1 = g_bn_b[mhi];
        float rs0 = 0.f, rs1 = 0.f;
        size_t rowlo = ((size_t)b * CC + mlo) * HW;
        size_t rowhi = ((size_t)b * CC + mhi) * HW;
        #pragma unroll
        for (int j = 0; j < 4; j++) {
            int n = n0 + wn + j * 8 + (lane & 3) * 2;
            float y00 = fmaxf(fmaf(acc[i][j][0], a0, c0), 0.f);
            float y01 = fmaxf(fmaf(acc[i][j][1], a0, c0), 0.f);
            float y10 = fmaxf(fmaf(acc[i][j][2], a1, c1), 0.f);
            float y11 = fmaxf(fmaf(acc[i][j][3], a1, c1), 0.f);
            float2 s0 = {y00, y01}; float2 s1 = {y10, y11};
            *(float2*)&g_feat[rowlo + n] = s0;
            *(float2*)&g_feat[rowhi + n] = s1;
            __nv_bfloat162 h0, h1, l0v, l1v;
            h0.x = __float2bfloat16(y00); h0.y = __float2bfloat16(y01);
            h1.x = __float2bfloat16(y10); h1.y = __float2bfloat16(y11);
            l0v.x = __float2bfloat16(y00 - __bfloat162float(h0.x));
            l0v.y = __float2bfloat16(y01 - __bfloat162float(h0.y));
            l1v.x = __float2bfloat16(y10 - __bfloat162float(h1.x));
            l1v.y = __float2bfloat16(y11 - __bfloat162float(h1.y));
            *(__nv_bfloat162*)&g_fhi[rowlo + n] = h0;
            *(__nv_bfloat162*)&g_fhi[rowhi + n] = h1;
            *(__nv_bfloat162*)&g_flo[rowlo + n] = l0v;
            *(__nv_bfloat162*)&g_flo[rowhi + n] = l1v;
            rs0 += y00 + y01; rs1 += y10 + y11;
        }
        rs0 += __shfl_xor_sync(0xFFFFFFFF, rs0, 1);
        rs0 += __shfl_xor_sync(0xFFFFFFFF, rs0, 2);
        rs1 += __shfl_xor_sync(0xFFFFFFFF, rs1, 1);
        rs1 += __shfl_xor_sync(0xFFFFFFFF, rs1, 2);
        if ((lane & 3) == 0) {
            atomicAdd(&g_fsum[b * CC + mlo], rs0);
            atomicAdd(&g_fsum[b * CC + mhi], rs1);
        }
    }
}

// ---------------------------------------------------------------
// K2: QK[64x128] = Wqk @ feat via HMMA; L2-norm per pixel; knsum
//     A = qkwT hi/lo [c][m] cp.async ; B = feat hi/lo [c][n] cp.async
// SMEM: A [2s][2h][32k][128B]=16K ; B @16384 [2s][2h][32k][256B]=32K ;
//       qk fp32 @49152 [64][129]=33024 ; part @82176 [32][8]=1024 ; tot 83200
// ---------------------------------------------------------------
#define QK_SMEM 83200
__global__ __launch_bounds__(256, 1) void k_qk_mma(const float* __restrict__ qb,
                                                   const float* __restrict__ kb) {
    extern __shared__ __align__(128) char smem[];
    const uint32_t smemb = smem_u32(smem);
    const int t    = threadIdx.x;
    const int lane = t & 31;
    const int wid  = t >> 5;
    const int n0   = blockIdx.x * 128;
    const int b    = blockIdx.y;
    const int wm   = (wid >> 2) * 32;   // 0 or 32
    const int wn   = (wid & 3) * 32;    // 0..96

    float acc[2][4][4];
    #pragma unroll
    for (int i = 0; i < 2; i++)
        #pragma unroll
        for (int j = 0; j < 4; j++)
            #pragma unroll
            for (int q = 0; q < 4; q++) acc[i][j][q] = 0.f;

    auto loadAB = [&](int kc, int s) {
        #pragma unroll
        for (int p = 0; p < 2; p++) {   // A: 512 16B ops
            int idx = t + p * 256;
            int h = idx >> 8, rem = idx & 255;
            int r = rem >> 3, c = rem & 7;
            const __nv_bfloat16* src = (h ? g_qkwlo : g_qkwhi) + (kc * 32 + r) * 64 + c * 8;
            CP_ASYNC16(smemb + s * 8192 + h * 4096 + r * 128 + ((c ^ (r & 7)) << 4), src);
        }
        #pragma unroll
        for (int p = 0; p < 4; p++) {   // B: 1024 16B ops
            int idx = t + p * 256;
            int h = idx >> 9, rem = idx & 511;
            int r = rem >> 4, c = rem & 15;
            const __nv_bfloat16* src = (h ? g_flo : g_fhi)
                + ((size_t)b * CC + kc * 32 + r) * HW + n0 + c * 8;
            CP_ASYNC16(smemb + 16384 + s * 16384 + h * 8192 + r * 256 + ((c ^ (r & 7)) << 4), src);
        }
        CP_COMMIT();
    };

    loadAB(0, 0);

    for (int kc = 0; kc < 8; kc++) {
        const int s = kc & 1;
        if (kc < 7) { loadAB(kc + 1, s ^ 1); CP_WAIT(1); }
        else        { CP_WAIT(0); }
        __syncthreads();

        const int l = lane & 7, g = lane >> 3;
        #pragma unroll
        for (int ks8 = 0; ks8 < 2; ks8++) {
            const int ks = ks8 * 16;
            uint32_t Bh[4][2], Bl[4][2];
            #pragma unroll
            for (int h = 0; h < 2; h++)
                #pragma unroll
                for (int jp = 0; jp < 2; jp++) {
                    int r = ks + ((g & 1) << 3) + l;
                    int c = (wn >> 3) + jp * 2 + (g >> 1);
                    uint32_t ad = smemb + 16384 + s * 16384 + h * 8192
                                + r * 256 + ((c ^ (r & 7)) << 4);
                    uint32_t q0, q1, q2, q3;
                    LDSM_X4_T(q0, q1, q2, q3, ad);
                    if (h == 0) { Bh[jp*2][0]=q0; Bh[jp*2][1]=q1; Bh[jp*2+1][0]=q2; Bh[jp*2+1][1]=q3; }
                    else        { Bl[jp*2][0]=q0; Bl[jp*2][1]=q1; Bl[jp*2+1][0]=q2; Bl[jp*2+1][1]=q3; }
                }
            #pragma unroll
            for (int i = 0; i < 2; i++) {
                uint32_t Ah[4], Al[4];
                {
                    int r = ks + ((g >> 1) << 3) + l;
                    int c = ((wm + i * 16) >> 3) + (g & 1);
                    uint32_t boff = r * 128 + ((c ^ (r & 7)) << 4);
                    LDSM_X4_T(Ah[0], Ah[1], Ah[2], Ah[3], smemb + s * 8192 + boff);
                    LDSM_X4_T(Al[0], Al[1], Al[2], Al[3], smemb + s * 8192 + 4096 + boff);
                }
                #pragma unroll
                for (int j = 0; j < 4; j++) {
                    MMA16816(acc[i][j], Ah, Bh[j]);
                    MMA16816(acc[i][j], Ah, Bl[j]);
                    MMA16816(acc[i][j], Al, Bh[j]);
                }
            }
        }
        __syncthreads();
    }

    // ---- stage QK tile (with bias) to smem ----
    float* qk = (float*)(smem + 49152);   // [64][129]
    #pragma unroll
    for (int i = 0; i < 2; i++) {
        int mlo = wm + i * 16 + (lane >> 2);
        int mhi = mlo + 8;
        float blo = (mlo < 32) ? qb[mlo] : kb[mlo - 32];
        float bhi = (mhi < 32) ? qb[mhi] : kb[mhi - 32];
        #pragma unroll
        for (int j = 0; j < 4; j++) {
            int col = wn + j * 8 + (lane & 3) * 2;
            qk[mlo * 129 + col]     = acc[i][j][0] + blo;
            qk[mlo * 129 + col + 1] = acc[i][j][1] + blo;
            qk[mhi * 129 + col]     = acc[i][j][2] + bhi;
            qk[mhi * 129 + col + 1] = acc[i][j][3] + bhi;
        }
    }
    __syncthreads();

    // ---- per-pixel L2 normalize ----
    {
        int n = t & 127, h = t >> 7;
        float ss = 0.f;
        #pragma unroll
        for (int m = 0; m < 32; m++) { float v = qk[(h * 32 + m) * 129 + n]; ss = fmaf(v, v, ss); }
        float inv = rsqrtf(ss);
        size_t base = (size_t)b * CQ * HW + n0 + n;
        if (h == 0) {
            #pragma unroll
            for (int m = 0; m < 32; m++)
                g_Qn[base + (size_t)m * HW] = qk[m * 129 + n] * inv;
        } else {
            #pragma unroll
            for (int m = 0; m < 32; m++) {
                float v = qk[(32 + m) * 129 + n] * inv;
                qk[(32 + m) * 129 + n] = v;
                __nv_bfloat16 vh = __float2bfloat16(v);
                g_knhi[base + (size_t)m * HW] = vh;
                g_knlo[base + (size_t)m * HW] = __float2bfloat16(v - __bfloat162float(vh));
            }
        }
    }
    __syncthreads();
    float* part = (float*)(smem + 82176);  // [32][8]
    {
        int m = t >> 3, seg = t & 7;
        float s = 0.f;
        #pragma unroll
        for (int j = 0; j < 16; j++) s += qk[(32 + m) * 129 + seg * 16 + j];
        part[m * 8 + seg] = s;
    }
    __syncthreads();
    if (t < 32) {
        float s = 0.f;
        #pragma unroll
        for (int j = 0; j < 8; j++) s += part[t * 8 + j];
        atomicAdd(&g_knsum[b * CQ + t], s);
    }
}

// ---------------------------------------------------------------
// K3: G^T[c][m] = sum_n feat[c][n]*Kn[m][n] via HMMA, non-trans ldmatrix
//     A = feat hi/lo [c][n-chunk64], B = Kn hi/lo [m][n-chunk64], K=n
// SMEM: A [2s][2h][256r][128B]=128K ; B @131072 [2s][2h][32r][128B]=16K ; 144K
// ---------------------------------------------------------------
#define G_SMEM 147456
__global__ __launch_bounds__(256, 1) void k_G_mma() {
    extern __shared__ __align__(128) char smem[];
    const uint32_t smemb = smem_u32(smem);
    const int t    = threadIdx.x;
    const int lane = t & 31;
    const int wid  = t >> 5;
    const int b    = blockIdx.y;
    const int n0   = blockIdx.x * 512;
    const int wc   = wid * 32;            // channel tile per warp

    float acc[2][4][4];
    #pragma unroll
    for (int i = 0; i < 2; i++)
        #pragma unroll
        for (int j = 0; j < 4; j++)
            #pragma unroll
            for (int q = 0; q < 4; q++) acc[i][j][q] = 0.f;

    auto loadAB = [&](int kc, int s) {
        int nb = n0 + kc * 64;
        #pragma unroll
        for (int p = 0; p < 16; p++) {   // A (feat): 4096 16B ops
            int idx = t + p * 256;
            int h = idx >> 11, rem = idx & 2047;
            int r = rem >> 3, c = rem & 7;
            const __nv_bfloat16* src = (h ? g_flo : g_fhi)
                + ((size_t)b * CC + r) * HW + nb + c * 8;
            CP_ASYNC16(smemb + s * 65536 + h * 32768 + r * 128 + ((c ^ (r & 7)) << 4), src);
        }
        #pragma unroll
        for (int p = 0; p < 2; p++) {    // B (Kn): 512 16B ops
            int idx = t + p * 256;
            int h = idx >> 8, rem = idx & 255;
            int r = rem >> 3, c = rem & 7;
            const __nv_bfloat16* src = (h ? g_knlo : g_knhi)
                + ((size_t)b * CQ + r) * HW + nb + c * 8;
            CP_ASYNC16(smemb + 131072 + s * 8192 + h * 4096 + r * 128 + ((c ^ (r & 7)) << 4), src);
        }
        CP_COMMIT();
    };

    loadAB(0, 0);

    for (int kc = 0; kc < 8; kc++) {
        const int s = kc & 1;
        if (kc < 7) { loadAB(kc + 1, s ^ 1); CP_WAIT(1); }
        else        { CP_WAIT(0); }
        __syncthreads();

        #pragma unroll
        for (int ks8 = 0; ks8 < 4; ks8++) {
            const int kcol0 = ks8 * 2;    // 16-byte col index (k>>3)
            uint32_t Bh[4][2], Bl[4][2];
            #pragma unroll
            for (int h = 0; h < 2; h++)
                #pragma unroll
                for (int jp = 0; jp < 2; jp++) {
                    int r = jp * 16 + ((lane & 16) >> 1) + (lane & 7);
                    int c = kcol0 + ((lane & 8) >> 3);
                    uint32_t ad = smemb + 131072 + s * 8192 + h * 4096
                                + r * 128 + ((c ^ (r & 7)) << 4);
                    uint32_t q0, q1, q2, q3;
                    LDSM_X4(q0, q1, q2, q3, ad);
                    if (h == 0) { Bh[jp*2][0]=q0; Bh[jp*2][1]=q1; Bh[jp*2+1][0]=q2; Bh[jp*2+1][1]=q3; }
                    else        { Bl[jp*2][0]=q0; Bl[jp*2][1]=q1; Bl[jp*2+1][0]=q2; Bl[jp*2+1][1]=q3; }
                }
            #pragma unroll
            for (int i = 0; i < 2; i++) {
                uint32_t Ah[4], Al[4];
                {
                    int r = wc + i * 16 + (lane & 15);
                    int c = kcol0 + ((lane & 16) >> 4);
                    uint32_t boff = r * 128 + ((c ^ (r & 7)) << 4);
                    LDSM_X4(Ah[0], Ah[1], Ah[2], Ah[3], smemb + s * 65536 + boff);
                    LDSM_X4(Al[0], Al[1], Al[2], Al[3], smemb + s * 65536 + 32768 + boff);
                }
                #pragma unroll
                for (int j = 0; j < 4; j++) {
                    MMA16816(acc[i][j], Ah, Bh[j]);
                    MMA16816(acc[i][j], Ah, Bl[j]);
                    MMA16816(acc[i][j], Al, Bh[j]);
                }
            }
        }
        __syncthreads();
    }

    // ---- epilogue: atomic accumulate into g_G[b][m][c] ----
    #pragma unroll
    for (int i = 0; i < 2; i++) {
        int clo = wc + i * 16 + (lane >> 2);
        int chi = clo + 8;
        #pragma unroll
        for (int j = 0; j < 4; j++) {
            int m = j * 8 + (lane & 3) * 2;
            atomicAdd(&g_G[((size_t)b * CQ + m)     * CC + clo], acc[i][j][0]);
            atomicAdd(&g_G[((size_t)b * CQ + m + 1) * CC + clo], acc[i][j][1]);
            atomicAdd(&g_G[((size_t)b * CQ + m)     * CC + chi], acc[i][j][2]);
            atomicAdd(&g_G[((size_t)b * CQ + m + 1) * CC + chi], acc[i][j][3]);
        }
    }
}

// ---------------------------------------------------------------
// K4: matrix = G @ v_w^T + v_b x knsum ; vsum = v_w @ fsum + N*v_b
// ---------------------------------------------------------------
__global__ __launch_bounds__(256) void k_matrix(const float* __restrict__ vw, const float* __restrict__ vb) {
    __shared__ __align__(16) float GsT[32][36];
    __shared__ __align__(16) float vwTs[32][256];
    __shared__ float fsums[256];
    const int t  = threadIdx.x;
    const int b  = blockIdx.x;
    const int tx = t & 31, ty = t >> 5;

    float acc[4][8];
    #pragma unroll
    for (int i = 0; i < 4; i++)
        #pragma unroll
        for (int j = 0; j < 8; j++) acc[i][j] = 0.f;
    float vs = 0.f;

    fsums[t] = g_fsum[b * CC + t];
    const int gm = t & 31;
    const int gc = (t >> 5) * 4;

    for (int c0 = 0; c0 < CC; c0 += 32) {
        float4 gv = *(const float4*)&g_G[((size_t)b * CQ + gm) * CC + c0 + gc];
        GsT[gc + 0][gm] = gv.x; GsT[gc + 1][gm] = gv.y;
        GsT[gc + 2][gm] = gv.z; GsT[gc + 3][gm] = gv.w;
        const float* vr = vw + (size_t)t * CC + c0;
        #pragma unroll
        for (int j = 0; j < 8; j++) {
            float4 vv = *(const float4*)&vr[j * 4];
            vwTs[j * 4 + 0][t] = vv.x; vwTs[j * 4 + 1][t] = vv.y;
            vwTs[j * 4 + 2][t] = vv.z; vwTs[j * 4 + 3][t] = vv.w;
        }
        __syncthreads();
        #pragma unroll
        for (int cl = 0; cl < 32; cl++) {
            float4 g4 = *(float4*)&GsT[cl][ty * 4];
            float4 v0 = *(float4*)&vwTs[cl][tx * 8];
            float4 v1 = *(float4*)&vwTs[cl][tx * 8 + 4];
            float gr[4] = {g4.x, g4.y, g4.z, g4.w};
            float vr8[8] = {v0.x, v0.y, v0.z, v0.w, v1.x, v1.y, v1.z, v1.w};
            #pragma unroll
            for (int i = 0; i < 4; i++)
                #pragma unroll
                for (int j = 0; j < 8; j++)
                    acc[i][j] = fmaf(gr[i], vr8[j], acc[i][j]);
            vs = fmaf(vwTs[cl][t], fsums[c0 + cl], vs);
        }
        __syncthreads();
    }
    float kn[4];
    #pragma unroll
    for (int i = 0; i < 4; i++) kn[i] = g_knsum[b * CQ + ty * 4 + i];
    #pragma unroll
    for (int i = 0; i < 4; i++)
        #pragma unroll
        for (int j = 0; j < 8; j++) {
            int c = tx * 8 + j;
            g_matrix[((size_t)b * CQ + ty * 4 + i) * CC + c] = acc[i][j] + vb[c] * kn[i];
        }
    g_vsum[b * CC + t] = vs + NPIXF * vb[t];
}

// ---------------------------------------------------------------
// K5: per pixel: ms = matrix^T @ Qn + vsum ; tailor ; fused epilogue
// ---------------------------------------------------------------
__global__ __launch_bounds__(256) void k_final(const float* __restrict__ gamma, float* __restrict__ out) {
    __shared__ __align__(16) float ms[32][256];
    __shared__ __align__(16) float Qns[32][64];
    __shared__ float tails[64];
    __shared__ float vsums[256];
    __shared__ float kse[32];
    const int t  = threadIdx.x;
    const int tx = t & 7, ty = t >> 3;
    const int n0 = blockIdx.x * 64;
    const int b  = blockIdx.y;

    {
        const float* mp = g_matrix + (size_t)b * CQ * CC;
        float* msf = &ms[0][0];
        #pragma unroll
        for (int j = 0; j < 8; j++) {
            int idx = t * 32 + j * 4;
            *(float4*)&msf[idx] = *(const float4*)&mp[idx];
        }
    }
    {
        int m = t >> 3, nl = (t & 7) * 8;
        const float* qp = g_Qn + ((size_t)b * CQ + m) * HW + n0 + nl;
        *(float4*)&Qns[m][nl]     = *(const float4*)&qp[0];
        *(float4*)&Qns[m][nl + 4] = *(const float4*)&qp[4];
    }
    vsums[t] = g_vsum[b * CC + t];
    if (t < 32) kse[t] = g_knsum[b * CQ + t] + 1e-6f;
    __syncthreads();
    if (t < 64) {
        float s = 0.f;
        #pragma unroll
        for (int m = 0; m < 32; m++) s = fmaf(Qns[m][t], kse[m], s);
        tails[t] = 1.0f / (NPIXF + s);
    }
    __syncthreads();

    float acc[8][8];
    #pragma unroll
    for (int i = 0; i < 8; i++)
        #pragma unroll
        for (int j = 0; j < 8; j++) acc[i][j] = 0.f;

    #pragma unroll 4
    for (int k = 0; k < 32; k++) {
        float4 m0v = *(float4*)&ms[k][ty * 8];
        float4 m1v = *(float4*)&ms[k][ty * 8 + 4];
        float4 q0  = *(float4*)&Qns[k][tx * 8];
        float4 q1  = *(float4*)&Qns[k][tx * 8 + 4];
        float mr[8] = {m0v.x, m0v.y, m0v.z, m0v.w, m1v.x, m1v.y, m1v.z, m1v.w};
        float qr[8] = {q0.x, q0.y, q0.z, q0.w, q1.x, q1.y, q1.z, q1.w};
        #pragma unroll
        for (int i = 0; i < 8; i++)
            #pragma unroll
            for (int j = 0; j < 8; j++)
                acc[i][j] = fmaf(mr[i], qr[j], acc[i][j]);
    }

    float gw = gamma[0];
    #pragma unroll
    for (int i = 0; i < 8; i++) {
        int c = ty * 8 + i;
        float vsc = vsums[c];
        size_t base = ((size_t)b * CC + c) * HW + n0 + tx * 8;
        float4 f0 = *(const float4*)&g_feat[base];
        float4 f1 = *(const float4*)&g_feat[base + 4];
        float fv[8] = {f0.x, f0.y, f0.z, f0.w, f1.x, f1.y, f1.z, f1.w};
        float o[8];
        #pragma unroll
        for (int j = 0; j < 8; j++) {
            float msv = acc[i][j] + vsc;
            float wv  = msv * tails[tx * 8 + j];
            float f   = fv[j];
            o[j] = fmaf(f, fmaf(gw, wv, f), f);
        }
        float4 s0 = {o[0], o[1], o[2], o[3]};
        float4 s1 = {o[4], o[5], o[6], o[7]};
        *(float4*)&out[base]     = s0;
        *(float4*)&out[base + 4] = s1;
    }
}

// ---------------------------------------------------------------
extern "C" void kernel_launch(void* const* d_in, const int* in_sizes, int n_in,
                              void* d_out, int out_size) {
    const float* fsp      = (const float*)d_in[0];
    const float* fcp      = (const float*)d_in[1];
    const float* conv_w   = (const float*)d_in[2];
    const float* bn_scale = (const float*)d_in[3];
    const float* bn_bias  = (const float*)d_in[4];
    const float* bn_mean  = (const float*)d_in[5];
    const float* bn_var   = (const float*)d_in[6];
    const float* gamma    = (const float*)d_in[7];
    const float* q_w      = (const float*)d_in[8];
    const float* q_b      = (const float*)d_in[9];
    const float* k_w      = (const float*)d_in[10];
    const float* k_b      = (const float*)d_in[11];
    const float* v_w      = (const float*)d_in[12];
    const float* v_b      = (const float*)d_in[13];
    float* out = (float*)d_out;

    cudaFuncSetAttribute(k_conv_mma, cudaFuncAttributeMaxDynamicSharedMemorySize, CONV_SMEM);
    cudaFuncSetAttribute(k_qk_mma,   cudaFuncAttributeMaxDynamicSharedMemorySize, QK_SMEM);
    cudaFuncSetAttribute(k_G_mma,    cudaFuncAttributeMaxDynamicSharedMemorySize, G_SMEM);

    k_setup<<<128, 256>>>(bn_scale, bn_bias, bn_mean, bn_var, conv_w, q_w, k_w);
    k_conv_mma<<<dim3(72, 16), 512, CONV_SMEM>>>(fsp, fcp);
    k_qk_mma  <<<dim3(72, 16), 256, QK_SMEM>>>(q_b, k_b);
    k_G_mma   <<<dim3(18, 16), 256, G_SMEM>>>();
    k_matrix  <<<16,           256>>>(v_w, v_b);
    k_final   <<<dim3(144, 16), 256>>>(gamma, out);
}

// round 11
// speedup vs baseline: 2.3930x; 1.1013x over previous
#include <cuda_runtime.h>
#include <cuda_bf16.h>
#include <cstdint>

#define BB   16
#define CC   256
#define CHALF 128
#define CQ   32
#define HW   9216
#define NPIXF 9216.0f

// ---- scratch (device globals; no runtime allocation allowed) ----
__device__ __align__(256) __nv_bfloat16 g_fhi[(size_t)BB*CC*HW];
__device__ __align__(256) __nv_bfloat16 g_flo[(size_t)BB*CC*HW];
__device__ __align__(256) __nv_bfloat16 g_qnhi[(size_t)BB*CQ*HW];
__device__ __align__(256) __nv_bfloat16 g_qnlo[(size_t)BB*CQ*HW];
__device__ __align__(256) __nv_bfloat16 g_knhi[(size_t)BB*CQ*HW];
__device__ __align__(256) __nv_bfloat16 g_knlo[(size_t)BB*CQ*HW];
__device__ __align__(256) __nv_bfloat16 g_whiT[CC*CC];    // W^T hi  [k][m]
__device__ __align__(256) __nv_bfloat16 g_wloT[CC*CC];    // W^T lo  [k][m]
__device__ __align__(256) __nv_bfloat16 g_qkwhi[CC*64];   // [c][m] m<32:q, else k
__device__ __align__(256) __nv_bfloat16 g_qkwlo[CC*64];
__device__ __align__(256) __nv_bfloat16 g_mthi[BB*CC*CQ]; // matrix^T [b][c][m]
__device__ __align__(256) __nv_bfloat16 g_mtlo[BB*CC*CQ];
__device__ float g_G  [BB*CQ*CC];
__device__ float g_fsum[BB*CC];
__device__ float g_knsum[BB*CQ];
__device__ float g_vsum[BB*CC];
__device__ float g_bn_a[CC];
__device__ float g_bn_b[CC];

// =================== PTX helpers (sm_80-era, legal on sm_103 PTX) ===================
__device__ __forceinline__ uint32_t smem_u32(const void* p) {
    uint32_t a;
    asm("{ .reg .u64 t; cvta.to.shared.u64 t, %1; cvt.u32.u64 %0, t; }" : "=r"(a) : "l"(p));
    return a;
}
#define CP_ASYNC16(dst, src) \
    asm volatile("cp.async.cg.shared.global [%0], [%1], 16;" :: "r"(dst), "l"(src) : "memory")
#define CP_COMMIT() asm volatile("cp.async.commit_group;" ::: "memory")
#define CP_WAIT(n)  asm volatile("cp.async.wait_group %0;" :: "n"(n) : "memory")

#define LDSM_X4_T(r0, r1, r2, r3, addr) \
    asm volatile("ldmatrix.sync.aligned.m8n8.x4.trans.shared.b16 {%0,%1,%2,%3}, [%4];" \
                 : "=r"(r0), "=r"(r1), "=r"(r2), "=r"(r3) : "r"(addr))
#define LDSM_X4(r0, r1, r2, r3, addr) \
    asm volatile("ldmatrix.sync.aligned.m8n8.x4.shared.b16 {%0,%1,%2,%3}, [%4];" \
                 : "=r"(r0), "=r"(r1), "=r"(r2), "=r"(r3) : "r"(addr))

#define MMA16816(d, a, b) \
    asm volatile("mma.sync.aligned.m16n8k16.row.col.f32.bf16.bf16.f32 " \
                 "{%0,%1,%2,%3}, {%4,%5,%6,%7}, {%8,%9}, {%0,%1,%2,%3};" \
                 : "+f"((d)[0]), "+f"((d)[1]), "+f"((d)[2]), "+f"((d)[3]) \
                 : "r"((a)[0]), "r"((a)[1]), "r"((a)[2]), "r"((a)[3]), \
                   "r"((b)[0]), "r"((b)[1]))

// ---------------------------------------------------------------
// K0: zero accumulators, fold BN, build bf16 hi/lo weights
// ---------------------------------------------------------------
__global__ void k_setup(const float* __restrict__ bn_scale, const float* __restrict__ bn_bias,
                        const float* __restrict__ bn_mean,  const float* __restrict__ bn_var,
                        const float* __restrict__ conv_w,
                        const float* __restrict__ qw, const float* __restrict__ kw) {
    int t = blockIdx.x * blockDim.x + threadIdx.x;
    int stride = gridDim.x * blockDim.x;
    for (int i = t; i < BB*CQ*CC; i += stride) g_G[i] = 0.f;
    for (int i = t; i < BB*CC;    i += stride) g_fsum[i] = 0.f;
    for (int i = t; i < BB*CQ;    i += stride) g_knsum[i] = 0.f;
    for (int i = t; i < CC*CC;    i += stride) {
        int k = i >> 8, m = i & 255;
        float w = conv_w[m * CC + k];
        __nv_bfloat16 hi = __float2bfloat16(w);
        g_whiT[i] = hi;
        g_wloT[i] = __float2bfloat16(w - __bfloat162float(hi));
    }
    for (int i = t; i < CC*64; i += stride) {
        int c = i >> 6, mm = i & 63;
        float w = (mm < 32) ? qw[mm * CC + c] : kw[(mm - 32) * CC + c];
        __nv_bfloat16 hi = __float2bfloat16(w);
        g_qkwhi[i] = hi;
        g_qkwlo[i] = __float2bfloat16(w - __bfloat162float(hi));
    }
    if (t < CC) {
        float inv = rsqrtf(bn_var[t] + 1e-5f);
        float a = bn_scale[t] * inv;
        g_bn_a[t] = a;
        g_bn_b[t] = bn_bias[t] - bn_mean[t] * a;
    }
}

// ---------------------------------------------------------------
// K1: conv1x1 + BN + ReLU via mma.sync bf16 (3-term split)
//     emits feat ONLY as bf16 hi/lo (consumers reconstruct)
// ---------------------------------------------------------------
#define CONV_SMEM 98304
__global__ __launch_bounds__(512, 1) void k_conv_mma(const float* __restrict__ fsp,
                                                     const float* __restrict__ fcp) {
    extern __shared__ __align__(128) char smem[];
    const uint32_t smemb = smem_u32(smem);
    const int t    = threadIdx.x;
    const int lane = t & 31;
    const int wid  = t >> 5;
    const int n0   = blockIdx.x * 128;
    const int b    = blockIdx.y;
    const int wm   = (wid >> 2) * 64;
    const int wn   = (wid & 3) * 32;

    float acc[4][4][4];
    #pragma unroll
    for (int i = 0; i < 4; i++)
        #pragma unroll
        for (int j = 0; j < 4; j++)
            #pragma unroll
            for (int q = 0; q < 4; q++) acc[i][j][q] = 0.f;

    const int xr = t >> 4;
    const int xc = (t & 15) * 8;
    float4 X0, X1;
    {
        int cg = xr;
        const float* p = (cg < CHALF ? fsp + ((size_t)b * CHALF + cg) * HW
                                     : fcp + ((size_t)b * CHALF + cg - CHALF) * HW) + n0 + xc;
        X0 = *(const float4*)p; X1 = *(const float4*)(p + 4);
    }

    auto loadA = [&](int kc, int s) {
        #pragma unroll
        for (int p = 0; p < 4; p++) {
            int idx = t + p * 512;
            int h = idx >> 10, rem = idx & 1023;
            int r = rem >> 5, c = rem & 31;
            const __nv_bfloat16* src =
                (h ? g_wloT : g_whiT) + (size_t)(kc * 32 + r) * CC + c * 8;
            uint32_t dst = smemb + s * 32768 + h * 16384 + r * 512 + ((c ^ (r & 7)) << 4);
            CP_ASYNC16(dst, src);
        }
        CP_COMMIT();
    };

    loadA(0, 0);

    for (int kc = 0; kc < 8; kc++) {
        const int s = kc & 1;
        {
            float xv[8] = {X0.x, X0.y, X0.z, X0.w, X1.x, X1.y, X1.z, X1.w};
            __align__(16) __nv_bfloat16 hi[8], lo[8];
            #pragma unroll
            for (int q = 0; q < 8; q++) {
                hi[q] = __float2bfloat16(xv[q]);
                lo[q] = __float2bfloat16(xv[q] - __bfloat162float(hi[q]));
            }
            int c = t & 15;
            uint32_t off = 65536 + s * 16384 + xr * 256 + ((c ^ (xr & 7)) << 4);
            *(uint4*)(smem + off)        = *(uint4*)hi;
            *(uint4*)(smem + off + 8192) = *(uint4*)lo;
        }
        if (kc < 7) { loadA(kc + 1, s ^ 1); CP_WAIT(1); }
        else        { CP_WAIT(0); }
        __syncthreads();

        if (kc < 7) {
            int cg = (kc + 1) * 32 + xr;
            const float* p = (cg < CHALF ? fsp + ((size_t)b * CHALF + cg) * HW
                                         : fcp + ((size_t)b * CHALF + cg - CHALF) * HW) + n0 + xc;
            X0 = *(const float4*)p; X1 = *(const float4*)(p + 4);
        }

        const int l = lane & 7, g = lane >> 3;
        #pragma unroll
        for (int ks8 = 0; ks8 < 2; ks8++) {
            const int ks = ks8 * 16;
            uint32_t Bh[4][2], Bl[4][2];
            #pragma unroll
            for (int h = 0; h < 2; h++)
                #pragma unroll
                for (int jp = 0; jp < 2; jp++) {
                    int r = ks + ((g & 1) << 3) + l;
                    int c = (wn >> 3) + jp * 2 + (g >> 1);
                    uint32_t ad = smemb + 65536 + s * 16384 + h * 8192
                                + r * 256 + ((c ^ (r & 7)) << 4);
                    uint32_t q0, q1, q2, q3;
                    LDSM_X4_T(q0, q1, q2, q3, ad);
                    if (h == 0) { Bh[jp*2][0]=q0; Bh[jp*2][1]=q1; Bh[jp*2+1][0]=q2; Bh[jp*2+1][1]=q3; }
                    else        { Bl[jp*2][0]=q0; Bl[jp*2][1]=q1; Bl[jp*2+1][0]=q2; Bl[jp*2+1][1]=q3; }
                }
            #pragma unroll
            for (int i = 0; i < 4; i++) {
                uint32_t Ah[4], Al[4];
                {
                    int r = ks + ((g >> 1) << 3) + l;
                    int c = ((wm + i * 16) >> 3) + (g & 1);
                    uint32_t boff = r * 512 + ((c ^ (r & 7)) << 4);
                    LDSM_X4_T(Ah[0], Ah[1], Ah[2], Ah[3], smemb + s * 32768 + boff);
                    LDSM_X4_T(Al[0], Al[1], Al[2], Al[3], smemb + s * 32768 + 16384 + boff);
                }
                #pragma unroll
                for (int j = 0; j < 4; j++) {
                    MMA16816(acc[i][j], Ah, Bh[j]);
                    MMA16816(acc[i][j], Ah, Bl[j]);
                    MMA16816(acc[i][j], Al, Bh[j]);
                }
            }
        }
        __syncthreads();
    }

    // ---- epilogue: BN + ReLU, store feat bf16 hi/lo, fsum ----
    #pragma unroll
    for (int i = 0; i < 4; i++) {
        int mlo = wm + i * 16 + (lane >> 2);
        int mhi = mlo + 8;
        float a0 = g_bn_a[mlo], c0 = g_bn_b[mlo];
        float a1 = g_bn_a[mhi], c1 = g_bn_b[mhi];
        float rs0 = 0.f, rs1 = 0.f;
        size_t rowlo = ((size_t)b * CC + mlo) * HW;
        size_t rowhi = ((size_t)b * CC + mhi) * HW;
        #pragma unroll
        for (int j = 0; j < 4; j++) {
            int n = n0 + wn + j * 8 + (lane & 3) * 2;
            float y00 = fmaxf(fmaf(acc[i][j][0], a0, c0), 0.f);
            float y01 = fmaxf(fmaf(acc[i][j][1], a0, c0), 0.f);
            float y10 = fmaxf(fmaf(acc[i][j][2], a1, c1), 0.f);
            float y11 = fmaxf(fmaf(acc[i][j][3], a1, c1), 0.f);
            __nv_bfloat162 h0, h1, l0v, l1v;
            h0.x = __float2bfloat16(y00); h0.y = __float2bfloat16(y01);
            h1.x = __float2bfloat16(y10); h1.y = __float2bfloat16(y11);
            l0v.x = __float2bfloat16(y00 - __bfloat162float(h0.x));
            l0v.y = __float2bfloat16(y01 - __bfloat162float(h0.y));
            l1v.x = __float2bfloat16(y10 - __bfloat162float(h1.x));
            l1v.y = __float2bfloat16(y11 - __bfloat162float(h1.y));
            *(__nv_bfloat162*)&g_fhi[rowlo + n] = h0;
            *(__nv_bfloat162*)&g_fhi[rowhi + n] = h1;
            *(__nv_bfloat162*)&g_flo[rowlo + n] = l0v;
            *(__nv_bfloat162*)&g_flo[rowhi + n] = l1v;
            rs0 += y00 + y01; rs1 += y10 + y11;
        }
        rs0 += __shfl_xor_sync(0xFFFFFFFF, rs0, 1);
        rs0 += __shfl_xor_sync(0xFFFFFFFF, rs0, 2);
        rs1 += __shfl_xor_sync(0xFFFFFFFF, rs1, 1);
        rs1 += __shfl_xor_sync(0xFFFFFFFF, rs1, 2);
        if ((lane & 3) == 0) {
            atomicAdd(&g_fsum[b * CC + mlo], rs0);
            atomicAdd(&g_fsum[b * CC + mhi], rs1);
        }
    }
}

// ---------------------------------------------------------------
// K2: QK[64x128] = Wqk @ feat via HMMA; L2-norm; Qn/Kn as bf16 hi/lo; knsum
// ---------------------------------------------------------------
#define QK_SMEM 83200
__global__ __launch_bounds__(256, 1) void k_qk_mma(const float* __restrict__ qb,
                                                   const float* __restrict__ kb) {
    extern __shared__ __align__(128) char smem[];
    const uint32_t smemb = smem_u32(smem);
    const int t    = threadIdx.x;
    const int lane = t & 31;
    const int wid  = t >> 5;
    const int n0   = blockIdx.x * 128;
    const int b    = blockIdx.y;
    const int wm   = (wid >> 2) * 32;
    const int wn   = (wid & 3) * 32;

    float acc[2][4][4];
    #pragma unroll
    for (int i = 0; i < 2; i++)
        #pragma unroll
        for (int j = 0; j < 4; j++)
            #pragma unroll
            for (int q = 0; q < 4; q++) acc[i][j][q] = 0.f;

    auto loadAB = [&](int kc, int s) {
        #pragma unroll
        for (int p = 0; p < 2; p++) {
            int idx = t + p * 256;
            int h = idx >> 8, rem = idx & 255;
            int r = rem >> 3, c = rem & 7;
            const __nv_bfloat16* src = (h ? g_qkwlo : g_qkwhi) + (kc * 32 + r) * 64 + c * 8;
            CP_ASYNC16(smemb + s * 8192 + h * 4096 + r * 128 + ((c ^ (r & 7)) << 4), src);
        }
        #pragma unroll
        for (int p = 0; p < 4; p++) {
            int idx = t + p * 256;
            int h = idx >> 9, rem = idx & 511;
            int r = rem >> 4, c = rem & 15;
            const __nv_bfloat16* src = (h ? g_flo : g_fhi)
                + ((size_t)b * CC + kc * 32 + r) * HW + n0 + c * 8;
            CP_ASYNC16(smemb + 16384 + s * 16384 + h * 8192 + r * 256 + ((c ^ (r & 7)) << 4), src);
        }
        CP_COMMIT();
    };

    loadAB(0, 0);

    for (int kc = 0; kc < 8; kc++) {
        const int s = kc & 1;
        if (kc < 7) { loadAB(kc + 1, s ^ 1); CP_WAIT(1); }
        else        { CP_WAIT(0); }
        __syncthreads();

        const int l = lane & 7, g = lane >> 3;
        #pragma unroll
        for (int ks8 = 0; ks8 < 2; ks8++) {
            const int ks = ks8 * 16;
            uint32_t Bh[4][2], Bl[4][2];
            #pragma unroll
            for (int h = 0; h < 2; h++)
                #pragma unroll
                for (int jp = 0; jp < 2; jp++) {
                    int r = ks + ((g & 1) << 3) + l;
                    int c = (wn >> 3) + jp * 2 + (g >> 1);
                    uint32_t ad = smemb + 16384 + s * 16384 + h * 8192
                                + r * 256 + ((c ^ (r & 7)) << 4);
                    uint32_t q0, q1, q2, q3;
                    LDSM_X4_T(q0, q1, q2, q3, ad);
                    if (h == 0) { Bh[jp*2][0]=q0; Bh[jp*2][1]=q1; Bh[jp*2+1][0]=q2; Bh[jp*2+1][1]=q3; }
                    else        { Bl[jp*2][0]=q0; Bl[jp*2][1]=q1; Bl[jp*2+1][0]=q2; Bl[jp*2+1][1]=q3; }
                }
            #pragma unroll
            for (int i = 0; i < 2; i++) {
                uint32_t Ah[4], Al[4];
                {
                    int r = ks + ((g >> 1) << 3) + l;
                    int c = ((wm + i * 16) >> 3) + (g & 1);
                    uint32_t boff = r * 128 + ((c ^ (r & 7)) << 4);
                    LDSM_X4_T(Ah[0], Ah[1], Ah[2], Ah[3], smemb + s * 8192 + boff);
                    LDSM_X4_T(Al[0], Al[1], Al[2], Al[3], smemb + s * 8192 + 4096 + boff);
                }
                #pragma unroll
                for (int j = 0; j < 4; j++) {
                    MMA16816(acc[i][j], Ah, Bh[j]);
                    MMA16816(acc[i][j], Ah, Bl[j]);
                    MMA16816(acc[i][j], Al, Bh[j]);
                }
            }
        }
        __syncthreads();
    }

    float* qk = (float*)(smem + 49152);   // [64][129]
    #pragma unroll
    for (int i = 0; i < 2; i++) {
        int mlo = wm + i * 16 + (lane >> 2);
        int mhi = mlo + 8;
        float blo = (mlo < 32) ? qb[mlo] : kb[mlo - 32];
        float bhi = (mhi < 32) ? qb[mhi] : kb[mhi - 32];
        #pragma unroll
        for (int j = 0; j < 4; j++) {
            int col = wn + j * 8 + (lane & 3) * 2;
            qk[mlo * 129 + col]     = acc[i][j][0] + blo;
            qk[mlo * 129 + col + 1] = acc[i][j][1] + blo;
            qk[mhi * 129 + col]     = acc[i][j][2] + bhi;
            qk[mhi * 129 + col + 1] = acc[i][j][3] + bhi;
        }
    }
    __syncthreads();

    {
        int n = t & 127, h = t >> 7;
        float ss = 0.f;
        #pragma unroll
        for (int m = 0; m < 32; m++) { float v = qk[(h * 32 + m) * 129 + n]; ss = fmaf(v, v, ss); }
        float inv = rsqrtf(ss);
        size_t base = (size_t)b * CQ * HW + n0 + n;
        if (h == 0) {
            #pragma unroll
            for (int m = 0; m < 32; m++) {
                float v = qk[m * 129 + n] * inv;
                __nv_bfloat16 vh = __float2bfloat16(v);
                g_qnhi[base + (size_t)m * HW] = vh;
                g_qnlo[base + (size_t)m * HW] = __float2bfloat16(v - __bfloat162float(vh));
            }
        } else {
            #pragma unroll
            for (int m = 0; m < 32; m++) {
                float v = qk[(32 + m) * 129 + n] * inv;
                qk[(32 + m) * 129 + n] = v;
                __nv_bfloat16 vh = __float2bfloat16(v);
                g_knhi[base + (size_t)m * HW] = vh;
                g_knlo[base + (size_t)m * HW] = __float2bfloat16(v - __bfloat162float(vh));
            }
        }
    }
    __syncthreads();
    float* part = (float*)(smem + 82176);  // [32][8]
    {
        int m = t >> 3, seg = t & 7;
        float s = 0.f;
        #pragma unroll
        for (int j = 0; j < 16; j++) s += qk[(32 + m) * 129 + seg * 16 + j];
        part[m * 8 + seg] = s;
    }
    __syncthreads();
    if (t < 32) {
        float s = 0.f;
        #pragma unroll
        for (int j = 0; j < 8; j++) s += part[t * 8 + j];
        atomicAdd(&g_knsum[b * CQ + t], s);
    }
}

// ---------------------------------------------------------------
// K3: G^T[c][m] = sum_n feat[c][n]*Kn[m][n] via HMMA (non-trans ldmatrix)
// ---------------------------------------------------------------
#define G_SMEM 147456
__global__ __launch_bounds__(256, 1) void k_G_mma() {
    extern __shared__ __align__(128) char smem[];
    const uint32_t smemb = smem_u32(smem);
    const int t    = threadIdx.x;
    const int lane = t & 31;
    const int wid  = t >> 5;
    const int b    = blockIdx.y;
    const int n0   = blockIdx.x * 512;
    const int wc   = wid * 32;

    float acc[2][4][4];
    #pragma unroll
    for (int i = 0; i < 2; i++)
        #pragma unroll
        for (int j = 0; j < 4; j++)
            #pragma unroll
            for (int q = 0; q < 4; q++) acc[i][j][q] = 0.f;

    auto loadAB = [&](int kc, int s) {
        int nb = n0 + kc * 64;
        #pragma unroll
        for (int p = 0; p < 16; p++) {
            int idx = t + p * 256;
            int h = idx >> 11, rem = idx & 2047;
            int r = rem >> 3, c = rem & 7;
            const __nv_bfloat16* src = (h ? g_flo : g_fhi)
                + ((size_t)b * CC + r) * HW + nb + c * 8;
            CP_ASYNC16(smemb + s * 65536 + h * 32768 + r * 128 + ((c ^ (r & 7)) << 4), src);
        }
        #pragma unroll
        for (int p = 0; p < 2; p++) {
            int idx = t + p * 256;
            int h = idx >> 8, rem = idx & 255;
            int r = rem >> 3, c = rem & 7;
            const __nv_bfloat16* src = (h ? g_knlo : g_knhi)
                + ((size_t)b * CQ + r) * HW + nb + c * 8;
            CP_ASYNC16(smemb + 131072 + s * 8192 + h * 4096 + r * 128 + ((c ^ (r & 7)) << 4), src);
        }
        CP_COMMIT();
    };

    loadAB(0, 0);

    for (int kc = 0; kc < 8; kc++) {
        const int s = kc & 1;
        if (kc < 7) { loadAB(kc + 1, s ^ 1); CP_WAIT(1); }
        else        { CP_WAIT(0); }
        __syncthreads();

        #pragma unroll
        for (int ks8 = 0; ks8 < 4; ks8++) {
            const int kcol0 = ks8 * 2;
            uint32_t Bh[4][2], Bl[4][2];
            #pragma unroll
            for (int h = 0; h < 2; h++)
                #pragma unroll
                for (int jp = 0; jp < 2; jp++) {
                    int r = jp * 16 + ((lane & 16) >> 1) + (lane & 7);
                    int c = kcol0 + ((lane & 8) >> 3);
                    uint32_t ad = smemb + 131072 + s * 8192 + h * 4096
                                + r * 128 + ((c ^ (r & 7)) << 4);
                    uint32_t q0, q1, q2, q3;
                    LDSM_X4(q0, q1, q2, q3, ad);
                    if (h == 0) { Bh[jp*2][0]=q0; Bh[jp*2][1]=q1; Bh[jp*2+1][0]=q2; Bh[jp*2+1][1]=q3; }
                    else        { Bl[jp*2][0]=q0; Bl[jp*2][1]=q1; Bl[jp*2+1][0]=q2; Bl[jp*2+1][1]=q3; }
                }
            #pragma unroll
            for (int i = 0; i < 2; i++) {
                uint32_t Ah[4], Al[4];
                {
                    int r = wc + i * 16 + (lane & 15);
                    int c = kcol0 + ((lane & 16) >> 4);
                    uint32_t boff = r * 128 + ((c ^ (r & 7)) << 4);
                    LDSM_X4(Ah[0], Ah[1], Ah[2], Ah[3], smemb + s * 65536 + boff);
                    LDSM_X4(Al[0], Al[1], Al[2], Al[3], smemb + s * 65536 + 32768 + boff);
                }
                #pragma unroll
                for (int j = 0; j < 4; j++) {
                    MMA16816(acc[i][j], Ah, Bh[j]);
                    MMA16816(acc[i][j], Ah, Bl[j]);
                    MMA16816(acc[i][j], Al, Bh[j]);
                }
            }
        }
        __syncthreads();
    }

    #pragma unroll
    for (int i = 0; i < 2; i++) {
        int clo = wc + i * 16 + (lane >> 2);
        int chi = clo + 8;
        #pragma unroll
        for (int j = 0; j < 4; j++) {
            int m = j * 8 + (lane & 3) * 2;
            atomicAdd(&g_G[((size_t)b * CQ + m)     * CC + clo], acc[i][j][0]);
            atomicAdd(&g_G[((size_t)b * CQ + m + 1) * CC + clo], acc[i][j][1]);
            atomicAdd(&g_G[((size_t)b * CQ + m)     * CC + chi], acc[i][j][2]);
            atomicAdd(&g_G[((size_t)b * CQ + m + 1) * CC + chi], acc[i][j][3]);
        }
    }
}

// ---------------------------------------------------------------
// K4: matrix = G @ v_w^T + v_b x knsum  -> bf16 hi/lo in [c][m] layout;
//     vsum = v_w @ fsum + N*v_b
// ---------------------------------------------------------------
__global__ __launch_bounds__(256) void k_matrix(const float* __restrict__ vw, const float* __restrict__ vb) {
    __shared__ __align__(16) float GsT[32][36];
    __shared__ __align__(16) float vwTs[32][256];
    __shared__ float fsums[256];
    const int t  = threadIdx.x;
    const int b  = blockIdx.x;
    const int tx = t & 31, ty = t >> 5;

    float acc[4][8];
    #pragma unroll
    for (int i = 0; i < 4; i++)
        #pragma unroll
        for (int j = 0; j < 8; j++) acc[i][j] = 0.f;
    float vs = 0.f;

    fsums[t] = g_fsum[b * CC + t];
    const int gm = t & 31;
    const int gc = (t >> 5) * 4;

    for (int c0 = 0; c0 < CC; c0 += 32) {
        float4 gv = *(const float4*)&g_G[((size_t)b * CQ + gm) * CC + c0 + gc];
        GsT[gc + 0][gm] = gv.x; GsT[gc + 1][gm] = gv.y;
        GsT[gc + 2][gm] = gv.z; GsT[gc + 3][gm] = gv.w;
        const float* vr = vw + (size_t)t * CC + c0;
        #pragma unroll
        for (int j = 0; j < 8; j++) {
            float4 vv = *(const float4*)&vr[j * 4];
            vwTs[j * 4 + 0][t] = vv.x; vwTs[j * 4 + 1][t] = vv.y;
            vwTs[j * 4 + 2][t] = vv.z; vwTs[j * 4 + 3][t] = vv.w;
        }
        __syncthreads();
        #pragma unroll
        for (int cl = 0; cl < 32; cl++) {
            float4 g4 = *(float4*)&GsT[cl][ty * 4];
            float4 v0 = *(float4*)&vwTs[cl][tx * 8];
            float4 v1 = *(float4*)&vwTs[cl][tx * 8 + 4];
            float gr[4] = {g4.x, g4.y, g4.z, g4.w};
            float vr8[8] = {v0.x, v0.y, v0.z, v0.w, v1.x, v1.y, v1.z, v1.w};
            #pragma unroll
            for (int i = 0; i < 4; i++)
                #pragma unroll
                for (int j = 0; j < 8; j++)
                    acc[i][j] = fmaf(gr[i], vr8[j], acc[i][j]);
            vs = fmaf(vwTs[cl][t], fsums[c0 + cl], vs);
        }
        __syncthreads();
    }
    float kn[4];
    #pragma unroll
    for (int i = 0; i < 4; i++) kn[i] = g_knsum[b * CQ + ty * 4 + i];
    #pragma unroll
    for (int i = 0; i < 4; i++)
        #pragma unroll
        for (int j = 0; j < 8; j++) {
            int c = tx * 8 + j;
            float val = acc[i][j] + vb[c] * kn[i];
            __nv_bfloat16 hi = __float2bfloat16(val);
            size_t idx = ((size_t)b * CC + c) * CQ + ty * 4 + i;
            g_mthi[idx] = hi;
            g_mtlo[idx] = __float2bfloat16(val - __bfloat162float(hi));
        }
    g_vsum[b * CC + t] = vs + NPIXF * vb[t];
}

// ---------------------------------------------------------------
// K5: ms[c][n] = matrix^T @ Qn + vsum via HMMA (K=32); tailor; epilogue
//     A = mt hi/lo [c rows][m cols] (non-trans, k_G recipe)
//     B = Qn hi/lo [m rows][n cols] (trans, conv recipe)
// SMEM: A [2h][256][128B]=64K ; B @65536 [2h][32][256B]=16K ;
//       tails @81920 f[128]; vsums @82432 f[256]; total 83456
// ---------------------------------------------------------------
#define FIN_SMEM 83456
__global__ __launch_bounds__(512, 1) void k_final_mma(const float* __restrict__ gamma,
                                                      float* __restrict__ out) {
    extern __shared__ __align__(128) char smem[];
    const uint32_t smemb = smem_u32(smem);
    const int t    = threadIdx.x;
    const int lane = t & 31;
    const int wid  = t >> 5;
    const int n0   = blockIdx.x * 128;
    const int b    = blockIdx.y;
    const int wm   = (wid >> 2) * 64;   // c tile
    const int wn   = (wid & 3) * 32;    // n tile

    float* tails = (float*)(smem + 81920);
    float* vsums = (float*)(smem + 82432);

    // ---- loads (single shot, K=32) ----
    #pragma unroll
    for (int p = 0; p < 4; p++) {        // A: 2048 16B ops
        int idx = t + p * 512;
        int h = idx >> 10, rem = idx & 1023;
        int r = rem >> 2, c = rem & 3;
        const __nv_bfloat16* src = (h ? g_mtlo : g_mthi) + ((size_t)b * CC + r) * CQ + c * 8;
        CP_ASYNC16(smemb + h * 32768 + r * 128 + ((c ^ (r & 7)) << 4), src);
    }
    #pragma unroll
    for (int p = 0; p < 2; p++) {        // B: 1024 16B ops
        int idx = t + p * 512;
        int h = idx >> 9, rem = idx & 511;
        int r = rem >> 4, c = rem & 15;
        const __nv_bfloat16* src = (h ? g_qnlo : g_qnhi)
            + ((size_t)b * CQ + r) * HW + n0 + c * 8;
        CP_ASYNC16(smemb + 65536 + h * 8192 + r * 256 + ((c ^ (r & 7)) << 4), src);
    }
    CP_COMMIT();
    if (t < 256) vsums[t] = g_vsum[b * CC + t];
    CP_WAIT(0);
    __syncthreads();

    // ---- tailor per pixel (reconstruct Qn = hi + lo) ----
    if (t < 128) {
        int n = t;
        int cseg = n >> 3, off = (n & 7) * 2;
        float s = 0.f;
        #pragma unroll
        for (int m = 0; m < 32; m++) {
            uint32_t ad = 65536 + m * 256 + ((cseg ^ (m & 7)) << 4) + off;
            float qh = __bfloat162float(*(__nv_bfloat16*)(smem + ad));
            float ql = __bfloat162float(*(__nv_bfloat16*)(smem + ad + 8192));
            s = fmaf(qh + ql, g_knsum[b * CQ + m] + 1e-6f, s);
        }
        tails[n] = 1.0f / (NPIXF + s);
    }
    __syncthreads();

    // ---- HMMA: K=32 (2 k16 steps x 3 split terms) ----
    float acc[4][4][4];
    #pragma unroll
    for (int i = 0; i < 4; i++)
        #pragma unroll
        for (int j = 0; j < 4; j++)
            #pragma unroll
            for (int q = 0; q < 4; q++) acc[i][j][q] = 0.f;

    const int l = lane & 7, g = lane >> 3;
    #pragma unroll
    for (int ks8 = 0; ks8 < 2; ks8++) {
        const int ks = ks8 * 16;
        uint32_t Bh[4][2], Bl[4][2];
        #pragma unroll
        for (int h = 0; h < 2; h++)
            #pragma unroll
            for (int jp = 0; jp < 2; jp++) {
                int r = ks + ((g & 1) << 3) + l;
                int c = (wn >> 3) + jp * 2 + (g >> 1);
                uint32_t ad = smemb + 65536 + h * 8192 + r * 256 + ((c ^ (r & 7)) << 4);
                uint32_t q0, q1, q2, q3;
                LDSM_X4_T(q0, q1, q2, q3, ad);
                if (h == 0) { Bh[jp*2][0]=q0; Bh[jp*2][1]=q1; Bh[jp*2+1][0]=q2; Bh[jp*2+1][1]=q3; }
                else        { Bl[jp*2][0]=q0; Bl[jp*2][1]=q1; Bl[jp*2+1][0]=q2; Bl[jp*2+1][1]=q3; }
            }
        #pragma unroll
        for (int i = 0; i < 4; i++) {
            uint32_t Ah[4], Al[4];
            {
                int r = wm + i * 16 + (lane & 15);
                int c = ks8 * 2 + ((lane & 16) >> 4);
                uint32_t boff = r * 128 + ((c ^ (r & 7)) << 4);
                LDSM_X4(Ah[0], Ah[1], Ah[2], Ah[3], smemb + boff);
                LDSM_X4(Al[0], Al[1], Al[2], Al[3], smemb + 32768 + boff);
            }
            #pragma unroll
            for (int j = 0; j < 4; j++) {
                MMA16816(acc[i][j], Ah, Bh[j]);
                MMA16816(acc[i][j], Ah, Bl[j]);
                MMA16816(acc[i][j], Al, Bh[j]);
            }
        }
    }

    // ---- epilogue: wv = (ms+vsum)*tailor ; out = f*(f + g*wv) + f ----
    const float gw = gamma[0];
    #pragma unroll
    for (int i = 0; i < 4; i++) {
        int clo = wm + i * 16 + (lane >> 2);
        int chi = clo + 8;
        float vs0 = vsums[clo], vs1 = vsums[chi];
        size_t rowlo = ((size_t)b * CC + clo) * HW;
        size_t rowhi = ((size_t)b * CC + chi) * HW;
        #pragma unroll
        for (int j = 0; j < 4; j++) {
            int nl = wn + j * 8 + (lane & 3) * 2;
            int n  = n0 + nl;
            float t0 = tails[nl], t1 = tails[nl + 1];
            __nv_bfloat162 fh0 = *(__nv_bfloat162*)&g_fhi[rowlo + n];
            __nv_bfloat162 fl0 = *(__nv_bfloat162*)&g_flo[rowlo + n];
            __nv_bfloat162 fh1 = *(__nv_bfloat162*)&g_fhi[rowhi + n];
            __nv_bfloat162 fl1 = *(__nv_bfloat162*)&g_flo[rowhi + n];
            float f00 = __bfloat162float(fh0.x) + __bfloat162float(fl0.x);
            float f01 = __bfloat162float(fh0.y) + __bfloat162float(fl0.y);
            float f10 = __bfloat162float(fh1.x) + __bfloat162float(fl1.x);
            float f11 = __bfloat162float(fh1.y) + __bfloat162float(fl1.y);
            float w00 = (acc[i][j][0] + vs0) * t0;
            float w01 = (acc[i][j][1] + vs0) * t1;
            float w10 = (acc[i][j][2] + vs1) * t0;
            float w11 = (acc[i][j][3] + vs1) * t1;
            float2 o0, o1;
            o0.x = fmaf(f00, fmaf(gw, w00, f00), f00);
            o0.y = fmaf(f01, fmaf(gw, w01, f01), f01);
            o1.x = fmaf(f10, fmaf(gw, w10, f10), f10);
            o1.y = fmaf(f11, fmaf(gw, w11, f11), f11);
            *(float2*)&out[rowlo + n] = o0;
            *(float2*)&out[rowhi + n] = o1;
        }
    }
}

// ---------------------------------------------------------------
extern "C" void kernel_launch(void* const* d_in, const int* in_sizes, int n_in,
                              void* d_out, int out_size) {
    const float* fsp      = (const float*)d_in[0];
    const float* fcp      = (const float*)d_in[1];
    const float* conv_w   = (const float*)d_in[2];
    const float* bn_scale = (const float*)d_in[3];
    const float* bn_bias  = (const float*)d_in[4];
    const float* bn_mean  = (const float*)d_in[5];
    const float* bn_var   = (const float*)d_in[6];
    const float* gamma    = (const float*)d_in[7];
    const float* q_w      = (const float*)d_in[8];
    const float* q_b      = (const float*)d_in[9];
    const float* k_w      = (const float*)d_in[10];
    const float* k_b      = (const float*)d_in[11];
    const float* v_w      = (const float*)d_in[12];
    const float* v_b      = (const float*)d_in[13];
    float* out = (float*)d_out;

    cudaFuncSetAttribute(k_conv_mma,  cudaFuncAttributeMaxDynamicSharedMemorySize, CONV_SMEM);
    cudaFuncSetAttribute(k_qk_mma,    cudaFuncAttributeMaxDynamicSharedMemorySize, QK_SMEM);
    cudaFuncSetAttribute(k_G_mma,     cudaFuncAttributeMaxDynamicSharedMemorySize, G_SMEM);
    cudaFuncSetAttribute(k_final_mma, cudaFuncAttributeMaxDynamicSharedMemorySize, FIN_SMEM);

    k_setup<<<128, 256>>>(bn_scale, bn_bias, bn_mean, bn_var, conv_w, q_w, k_w);
    k_conv_mma <<<dim3(72, 16), 512, CONV_SMEM>>>(fsp, fcp);
    k_qk_mma   <<<dim3(72, 16), 256, QK_SMEM>>>(q_b, k_b);
    k_G_mma    <<<dim3(18, 16), 256, G_SMEM>>>();
    k_matrix   <<<16,           256>>>(v_w, v_b);
    k_final_mma<<<dim3(72, 16), 512, FIN_SMEM>>>(gamma, out);
}